// round 14
// baseline (speedup 1.0000x reference)
#include <cuda_runtime.h>
#include <cuda_fp16.h>
#include <math.h>
#include <stdint.h>

#define NEGV (-1e30f)

// ========================= static device scratch ============================
#define MAXMN (16384L * 2048L)
__device__ float g_D1[MAXMN];
__device__ float g_D2[MAXMN];
__device__ float g_D4[MAXMN];
__device__ float g_D5[MAXMN];
__device__ float g_S[64L * 256 * 256];
__device__ __half g_P0[MAXMN];
__device__ __half g_P1[MAXMN];
__device__ __half g_XA[MAXMN];
__device__ __half g_X[MAXMN];
__device__ __half g_E1[MAXMN];
__device__ __half g_E2[MAXMN];
#define SNN (64L * 256 * 256)
__device__ __half g_AN1[SNN];
__device__ __half g_AN2[SNN];
__device__ __half g_Sh[SNN];
__device__ __half g_STh[SNN];
#define WT_ELEMS 29360128L
__device__ __half g_WT[WT_ELEMS];

// ============================ PTX helpers ===================================
__device__ __forceinline__ uint32_t smem_u32(const void* p) {
    uint32_t a;
    asm("{ .reg .u64 t; cvta.to.shared.u64 t, %1; cvt.u32.u64 %0, t; }" : "=r"(a) : "l"(p));
    return a;
}
__device__ __forceinline__ void cpasync16(uint32_t dst, const void* src) {
    asm volatile("cp.async.cg.shared.global [%0], [%1], 16;" :: "r"(dst), "l"(src));
}
__device__ __forceinline__ void ldm4(uint32_t* r, uint32_t a) {
    asm volatile("ldmatrix.sync.aligned.m8n8.x4.shared.b16 {%0,%1,%2,%3}, [%4];"
                 : "=r"(r[0]), "=r"(r[1]), "=r"(r[2]), "=r"(r[3]) : "r"(a));
}
__device__ __forceinline__ void ldm4t(uint32_t* r, uint32_t a) {
    asm volatile("ldmatrix.sync.aligned.m8n8.x4.trans.shared.b16 {%0,%1,%2,%3}, [%4];"
                 : "=r"(r[0]), "=r"(r[1]), "=r"(r[2]), "=r"(r[3]) : "r"(a));
}
#define MMA(d, a, b0, b1)                                                    \
    asm volatile(                                                            \
        "mma.sync.aligned.m16n8k16.row.col.f32.f16.f16.f32 "                 \
        "{%0,%1,%2,%3}, {%4,%5,%6,%7}, {%8,%9}, {%0,%1,%2,%3};"              \
        : "+f"((d)[0]), "+f"((d)[1]), "+f"((d)[2]), "+f"((d)[3])             \
        : "r"((a)[0]), "r"((a)[1]), "r"((a)[2]), "r"((a)[3]),                \
          "r"(b0), "r"(b1))

// ==================== unified tensor-core fp16 GEMM =========================
// CTA 128x128, 8 warps of 64x32, K-step 32, 2-stage cp.async.
// __launch_bounds__(256,3): cap regs ~85 to fit 3 CTAs/SM (24 warps) for
// latency coverage — tensor duty was 45% at 2 CTAs/SM with nothing saturated.
enum {
    EP_F32_BIAS = 0,
    EP_F32_BIAS_RELU = 1,
    EP_F16 = 2,
    EP_F16_ACCUM = 3,
    EP_F32_MASK = 4,
    EP_GCONV = 5
};

#define MM_STAGE 20480
#define MM_SMEM (2 * MM_STAGE)

template <int BTRANS, int EPI>
__global__ __launch_bounds__(256, 3) void gmma(
    const __half* __restrict__ Ah, const __half* __restrict__ Bh,
    float* __restrict__ Cf, __half* __restrict__ Oh,
    const float* __restrict__ bias, const float* __restrict__ bias2,
    int K, int ldB, int ldC,
    long sA, long sB, long sC,
    const int* __restrict__ n1p, const int* __restrict__ n2p)
{
    constexpr uint32_t BOFF = 10240;

    extern __shared__ char smem[];
    const uint32_t sb = smem_u32(smem);
    const int tid = threadIdx.x;
    const int wid = tid >> 5, lane = tid & 31;
    const int wm = wid >> 2, wn = wid & 3;
    const int m0 = blockIdx.y << 7;
    const int n0 = blockIdx.x << 7;
    const int bz = blockIdx.z;
    const int NC = K >> 5;

    const __half* Ab = Ah + (long)bz * sA;
    const __half* Bb = Bh + (long)bz * sB;

    auto loadstage = [&](int c) {
        const uint32_t st_ = sb + (uint32_t)((c & 1) ? MM_STAGE : 0);
        const int kc_ = c << 5;
#pragma unroll
        for (int j = 0; j < 2; ++j) {
            const int i = tid + j * 256;
            const int r = i >> 2, cg = i & 3;
            const uint32_t so = r * 80 + cg * 16;
            const long go = (long)(m0 + r) * K + kc_ + cg * 8;
            cpasync16(st_ + so, Ab + go);
        }
        if (BTRANS) {
#pragma unroll
            for (int j = 0; j < 2; ++j) {
                const int i = tid + j * 256;
                const int r = i >> 4, ch = i & 15;
                const uint32_t so = r * 272 + ch * 16;
                const long go = (long)(kc_ + r) * ldB + n0 + ch * 8;
                cpasync16(st_ + BOFF + so, Bb + go);
            }
        } else {
#pragma unroll
            for (int j = 0; j < 2; ++j) {
                const int i = tid + j * 256;
                const int r = i >> 2, cg = i & 3;
                const uint32_t so = r * 80 + cg * 16;
                const long go = (long)(n0 + r) * K + kc_ + cg * 8;
                cpasync16(st_ + BOFF + so, Bb + go);
            }
        }
        asm volatile("cp.async.commit_group;" ::: "memory");
    };

    float acc[4][4][4];
#pragma unroll
    for (int a = 0; a < 4; a++)
#pragma unroll
        for (int b = 0; b < 4; b++)
#pragma unroll
            for (int c = 0; c < 4; c++) acc[a][b][c] = 0.f;

    loadstage(0);

    for (int c = 0; c < NC; ++c) {
        if (c + 1 < NC) loadstage(c + 1);

        if (c + 1 < NC) asm volatile("cp.async.wait_group 1;" ::: "memory");
        else            asm volatile("cp.async.wait_group 0;" ::: "memory");
        __syncthreads();

        const uint32_t st = sb + (uint32_t)((c & 1) ? MM_STAGE : 0);
        const uint32_t aA = st + (uint32_t)(wm * 64 * 80 + (lane & 15) * 80 + (lane >> 4) * 16);

#pragma unroll
        for (int kk = 0; kk < 2; ++kk) {
            uint32_t bh[8];
            if (BTRANS) {
#pragma unroll
                for (int g = 0; g < 2; ++g) {
                    const uint32_t ro = (uint32_t)(kk * 16 + (lane & 7) + ((lane >> 4) << 3)) * 272;
                    const uint32_t co = (uint32_t)(wn * 32 + g * 16 + (((lane >> 3) & 1) << 3)) * 2;
                    ldm4t(&bh[g * 4], st + BOFF + ro + co);
                }
            } else {
                const uint32_t aB = st + BOFF +
                    (uint32_t)(wn * 32 * 80 + (lane & 15) * 80 + (lane >> 4) * 16);
#pragma unroll
                for (int g = 0; g < 2; ++g)
                    ldm4(&bh[g * 4], aB + g * 1280 + kk * 32);
            }
#pragma unroll
            for (int mt = 0; mt < 4; ++mt) {
                uint32_t ah[4];
                ldm4(ah, aA + mt * 1280 + kk * 32);
#pragma unroll
                for (int nt = 0; nt < 4; ++nt) {
                    const int g = nt >> 1, o = nt & 1;
                    MMA(acc[mt][nt], ah, bh[g * 4 + o], bh[g * 4 + 2 + o]);
                }
            }
        }
        __syncthreads();
    }

    // ---- epilogue ----
    float* Cb = (Cf != nullptr) ? Cf + (long)bz * sC : nullptr;
    __half* Ohb = (Oh != nullptr) ? Oh + (long)bz * sC : nullptr;

    const int r_l = lane >> 2, c_l = (lane & 3) * 2;
    const int cb = n0 + wn * 32 + c_l;
    int r1 = 0, r2 = 0;
    if (EPI == EP_F32_MASK) { r1 = n1p[bz]; r2 = n2p[bz]; }
    const bool gconv_f16_half = (EPI == EP_GCONV) && (n0 < 2048);

#pragma unroll
    for (int mt = 0; mt < 4; ++mt) {
#pragma unroll
        for (int h = 0; h < 2; ++h) {
            const int row = m0 + wm * 64 + mt * 16 + h * 8 + r_l;
            const long rbase = (long)row * ldC;
#pragma unroll
            for (int nt = 0; nt < 4; ++nt) {
                float vx = acc[mt][nt][h * 2 + 0];
                float vy = acc[mt][nt][h * 2 + 1];
                const int col = cb + nt * 8;
                if (EPI == EP_GCONV) {
                    if (gconv_f16_half) {
                        vx = fmaxf(vx + bias[col], 0.f);
                        vy = fmaxf(vy + bias[col + 1], 0.f);
                        *(__half2*)(Ohb + rbase + col) =
                            __halves2half2(__float2half(vx), __float2half(vy));
                    } else {
                        float2 v;
                        v.x = fmaxf(vx + bias2[col - 2048], 0.f);
                        v.y = fmaxf(vy + bias2[col - 2047], 0.f);
                        *(float2*)(Cb + rbase + col - 2048) = v;
                    }
                    continue;
                }
                if (EPI == EP_F32_BIAS || EPI == EP_F32_BIAS_RELU) {
                    vx += bias[col];
                    vy += bias[col + 1];
                }
                if (EPI == EP_F32_BIAS_RELU) {
                    vx = fmaxf(vx, 0.f);
                    vy = fmaxf(vy, 0.f);
                }
                if (EPI == EP_F16_ACCUM) {
                    const float2 o = *(const float2*)(Cb + rbase + col);
                    vx += o.x;
                    vy += o.y;
                }
                if (EPI == EP_F32_MASK) {
                    const bool rv = row < r1;
                    vx = (rv && (col + 0) < r2) ? vx : NEGV;
                    vy = (rv && (col + 1) < r2) ? vy : NEGV;
                }
                if (EPI == EP_F32_BIAS || EPI == EP_F32_BIAS_RELU || EPI == EP_F32_MASK) {
                    float2 v;
                    v.x = vx;
                    v.y = vy;
                    *(float2*)(Cb + rbase + col) = v;
                } else {
                    *(__half2*)(Ohb + rbase + col) =
                        __halves2half2(__float2half(vx), __float2half(vy));
                }
            }
        }
    }
}

// =================== fp32 -> fp16 convert (feat only) =======================
__global__ void split_k(const float* __restrict__ x, __half* __restrict__ o, long n4)
{
    const long i = (long)blockIdx.x * blockDim.x + threadIdx.x;
    if (i >= n4) return;
    const float4 v = ((const float4*)x)[i];
    ((__half2*)o)[i * 2 + 0] = __halves2half2(__float2half(v.x), __float2half(v.y));
    ((__half2*)o)[i * 2 + 1] = __halves2half2(__float2half(v.z), __float2half(v.w));
}

// ============ weight transpose + fp16: W[K,N] -> [N,K] ======================
__global__ void tconv_k(const float* __restrict__ W, __half* __restrict__ o,
                        int K, int N)
{
    __shared__ float t[32][33];
    const int n0 = blockIdx.x << 5, k0 = blockIdx.y << 5;
    const int tx = threadIdx.x, ty = threadIdx.y;
#pragma unroll
    for (int r = 0; r < 4; ++r)
        t[ty + 8 * r][tx] = W[(long)(k0 + ty + 8 * r) * N + n0 + tx];
    __syncthreads();
#pragma unroll
    for (int r = 0; r < 4; ++r)
        o[(long)(n0 + ty + 8 * r) * K + k0 + tx] = __float2half(t[tx][ty + 8 * r]);
}

// ------ fused: column-L1-sum + normalized-A fp16 ----------------------------
__global__ void anprep_k(const float* __restrict__ A, __half* __restrict__ o)
{
    const int b = blockIdx.x, j = threadIdx.x;
    const long base = (long)b << 16;
    float s = 0.f;
#pragma unroll 8
    for (int i = 0; i < 256; i++) s += fabsf(A[base + i * 256 + j]);
    const float c = 1.f / fmaxf(s, 1e-12f);
#pragma unroll 4
    for (int i = 0; i < 256; i++)
        o[base + i * 256 + j] = __float2half(A[base + i * 256 + j] * c);
}

// ------------------- Sinkhorn row normalization (one warp per row) ---------
__global__ void sk_row(float* __restrict__ S, const int* __restrict__ n1)
{
    const int warp = (blockIdx.x * blockDim.x + threadIdx.x) >> 5;
    const int lane = threadIdx.x & 31;
    const int b = warp >> 8, i = warp & 255;
    if (i >= n1[b]) return;

    float4* row = (float4*)(S + (((long)(b * 256 + i)) << 8));
    float4 v0 = row[lane];
    float4 v1 = row[lane + 32];

    float m = fmaxf(fmaxf(fmaxf(v0.x, v0.y), fmaxf(v0.z, v0.w)),
                    fmaxf(fmaxf(v1.x, v1.y), fmaxf(v1.z, v1.w)));
#pragma unroll
    for (int o = 16; o; o >>= 1) m = fmaxf(m, __shfl_xor_sync(0xffffffffu, m, o));

    float s = expf(v0.x - m) + expf(v0.y - m) + expf(v0.z - m) + expf(v0.w - m)
            + expf(v1.x - m) + expf(v1.y - m) + expf(v1.z - m) + expf(v1.w - m);
#pragma unroll
    for (int o = 16; o; o >>= 1) s += __shfl_xor_sync(0xffffffffu, s, o);

    const float lse = m + logf(s);
    v0.x -= lse; v0.y -= lse; v0.z -= lse; v0.w -= lse;
    v1.x -= lse; v1.y -= lse; v1.z -= lse; v1.w -= lse;
    row[lane] = v0;
    row[lane + 32] = v1;
}

// --------- Sinkhorn column pass.  MODE 0: inner; 1: final->fp32 out;
// --------- 2: final-> S, S^T fp16                                 -----------
template <int MODE>
__global__ void sk_col(float* __restrict__ S, const int* __restrict__ n2,
                       float* __restrict__ out,
                       __half* __restrict__ Sh, __half* __restrict__ STh)
{
    const int b = blockIdx.y;
    const int tx = threadIdx.x & 31;
    const int ty = threadIdx.x >> 5;
    const int j = (blockIdx.x << 5) + tx;

    float* base = S + ((long)b << 16);
    float v[32];
#pragma unroll
    for (int r = 0; r < 32; r++) v[r] = base[(ty * 32 + r) * 256 + j];

    float m = -3.4e38f;
#pragma unroll
    for (int r = 0; r < 32; r++) m = fmaxf(m, v[r]);

    __shared__ float red[8][32];
    red[ty][tx] = m;
    __syncthreads();
    float mt = red[0][tx];
#pragma unroll
    for (int k = 1; k < 8; k++) mt = fmaxf(mt, red[k][tx]);

    float s = 0.f;
#pragma unroll
    for (int r = 0; r < 32; r++) s += expf(v[r] - mt);
    __syncthreads();
    red[ty][tx] = s;
    __syncthreads();
    float st = red[0][tx];
#pragma unroll
    for (int k = 1; k < 8; k++) st += red[k][tx];

    const float lse = mt + logf(st);
    const bool cv = j < n2[b];

    if (MODE == 1) {
        float* ob = out + ((long)b << 16);
#pragma unroll
        for (int r = 0; r < 32; r++)
            ob[(ty * 32 + r) * 256 + j] = cv ? expf(v[r] - lse) : 0.f;
    } else if (MODE == 2) {
        const long bb = (long)b << 16;
#pragma unroll
        for (int r = 0; r < 32; r++) {
            const int rg = ty * 32 + r;
            const float e = cv ? expf(v[r] - lse) : 0.f;
            const __half h = __float2half(e);
            Sh[bb + rg * 256 + j] = h;
            STh[bb + (long)j * 256 + rg] = h;
        }
    } else {
        if (cv) {
#pragma unroll
            for (int r = 0; r < 32; r++) base[(ty * 32 + r) * 256 + j] = v[r] - lse;
        }
    }
}

// ---------------------------- host-side helpers ----------------------------
typedef __half hf;

template <int BT, int EPI>
static inline void GM(const hf* Ah, const hf* Bh,
                      float* Cf, hf* Oh, const float* bias,
                      int M, int N, int K, int batch, int ldB, int ldC,
                      long sA, long sB, long sC,
                      const int* n1 = nullptr, const int* n2 = nullptr,
                      const float* bias2 = nullptr)
{
    cudaFuncSetAttribute(gmma<BT, EPI>, cudaFuncAttributeMaxDynamicSharedMemorySize, MM_SMEM);
    dim3 grid(N / 128, M / 128, batch);
    gmma<BT, EPI><<<grid, 256, MM_SMEM>>>(Ah, Bh, Cf, Oh, bias, bias2,
                                          K, ldB, ldC, sA, sB, sC, n1, n2);
}

static inline void SPLIT(const float* x, hf* o, long n)
{
    const long n4 = n >> 2;
    split_k<<<(unsigned)((n4 + 255) / 256), 256>>>(x, o, n4);
}

static inline void TCONV(const float* W, hf* o, int K, int N)
{
    dim3 grid(N / 32, K / 32);
    tconv_k<<<grid, dim3(32, 8)>>>(W, o, K, N);
}

extern "C" void kernel_launch(void* const* d_in, const int* in_sizes, int n_in,
                              void* d_out, int out_size)
{
    const float* feat1   = (const float*)d_in[0];
    const float* feat2   = (const float*)d_in[1];
    const float* A1      = (const float*)d_in[2];
    const float* A2      = (const float*)d_in[3];
    const float* g0_aW   = (const float*)d_in[4];
    const float* g0_ab   = (const float*)d_in[5];
    const float* g0_uW   = (const float*)d_in[6];
    const float* g0_ub   = (const float*)d_in[7];
    const float* g1_aW   = (const float*)d_in[8];
    const float* g1_ab   = (const float*)d_in[9];
    const float* g1_uW   = (const float*)d_in[10];
    const float* g1_ub   = (const float*)d_in[11];
    const float* aff0_W  = (const float*)d_in[12];
    const float* aff1_W  = (const float*)d_in[13];
    const float* cross_W = (const float*)d_in[14];
    const float* cross_b = (const float*)d_in[15];
    const int*   n1      = (const int*)d_in[16];
    const int*   n2      = (const int*)d_in[17];
    float*       out     = (float*)d_out;

    float *D1, *D2, *D4, *D5, *S;
    hf *P0, *P1, *XA, *X, *E1, *E2, *AN1, *AN2, *Sh, *STh, *WT;
    cudaGetSymbolAddress((void**)&D1, g_D1);
    cudaGetSymbolAddress((void**)&D2, g_D2);
    cudaGetSymbolAddress((void**)&D4, g_D4);
    cudaGetSymbolAddress((void**)&D5, g_D5);
    cudaGetSymbolAddress((void**)&S, g_S);
    cudaGetSymbolAddress((void**)&P0, g_P0);
    cudaGetSymbolAddress((void**)&P1, g_P1);
    cudaGetSymbolAddress((void**)&XA, g_XA);
    cudaGetSymbolAddress((void**)&X, g_X);
    cudaGetSymbolAddress((void**)&E1, g_E1);
    cudaGetSymbolAddress((void**)&E2, g_E2);
    cudaGetSymbolAddress((void**)&AN1, g_AN1);
    cudaGetSymbolAddress((void**)&AN2, g_AN2);
    cudaGetSymbolAddress((void**)&Sh, g_Sh);
    cudaGetSymbolAddress((void**)&STh, g_STh);
    cudaGetSymbolAddress((void**)&WT, g_WT);

    const int IN = 1024, HID = 2048;
    const int M = 16384;
    const long sNN = 65536;
    const long sNH = 524288;

    const long o_g0a = 0, o_g0u = 2097152, o_g1a = 4194304, o_g1u = 8388608;
    const long o_af0 = 12582912, o_af1 = 16777216, o_cT = 20971520, o_cB = 25165824;

    // ---- prologue: launch index 3 is a big fc gmma (capture lands at 3) ----
    TCONV(g0_aW, WT + o_g0a, IN, HID);        // 0
    SPLIT(feat1, P0, (long)M * IN);           // 1
    TCONV(g0_uW, WT + o_g0u, IN, HID);        // 2

    // ---- layer 0, graph 1 (fused aW|uW, N=4096) ----
    GM<0, EP_GCONV>(P0, WT + o_g0a, D1, XA,
                    g0_ab, M, 4096, IN, 1, 0, HID, 0, 0, 0, nullptr, nullptr, g0_ub);  // 3
    anprep_k<<<64, 256>>>(A1, AN1);
    GM<1, EP_F16_ACCUM>(AN1, XA, D1, E1, nullptr,
                        256, HID, 256, 64, HID, HID, sNN, sNH, sNH);

    // ---- layer 0, graph 2 ----
    SPLIT(feat2, P1, (long)M * IN);
    GM<0, EP_GCONV>(P1, WT + o_g0a, D2, XA,
                    g0_ab, M, 4096, IN, 1, 0, HID, 0, 0, 0, nullptr, nullptr, g0_ub);
    anprep_k<<<64, 256>>>(A2, AN2);
    GM<1, EP_F16_ACCUM>(AN2, XA, D2, E2, nullptr,
                        256, HID, 256, 64, HID, HID, sNN, sNH, sNH);

    // remaining weight prep
    TCONV(g1_aW, WT + o_g1a, HID, HID);
    TCONV(g1_uW, WT + o_g1u, HID, HID);
    TCONV(aff0_W, WT + o_af0, HID, HID);
    TCONV(aff1_W, WT + o_af1, HID, HID);
    TCONV(cross_W, WT + o_cT, HID, HID);
    TCONV(cross_W + (long)HID * HID, WT + o_cB, HID, HID);

    // ---- affinity 0 + Sinkhorn 1 (emits S, S^T fp16) ----
    GM<0, EP_F16>(E1, WT + o_af0, nullptr, X, nullptr,
                  M, HID, HID, 1, 0, HID, 0, 0, 0);
    GM<0, EP_F32_MASK>(X, E2, S, nullptr, nullptr,
                       256, 256, HID, 64, 0, 256, sNH, sNH, sNN, n1, n2);
    for (int it = 0; it < 10; ++it) {
        if (!(it & 1))    sk_row<<<2048, 256>>>(S, n1);
        else if (it == 9) sk_col<2><<<dim3(8, 64), 256>>>(S, n2, nullptr, Sh, STh);
        else              sk_col<0><<<dim3(8, 64), 256>>>(S, n2, nullptr, nullptr, nullptr);
    }

    // ---- cross-graph update ----
    GM<1, EP_F16>(Sh, E2, nullptr, X, nullptr,
                  256, HID, 256, 64, HID, HID, sNN, sNH, sNH);   // S @ emb2
    GM<0, EP_F32_BIAS>(E1, WT + o_cT, D4, nullptr,
                       cross_b, M, HID, HID, 1, 0, HID, 0, 0, 0);
    GM<0, EP_F16_ACCUM>(X, WT + o_cB, D4, P0, nullptr,
                        M, HID, HID, 1, 0, HID, 0, 0, 0);        // new_emb1 -> P0
    GM<1, EP_F16>(STh, E1, nullptr, X, nullptr,
                  256, HID, 256, 64, HID, HID, sNN, sNH, sNH);   // S^T @ emb1
    GM<0, EP_F32_BIAS>(E2, WT + o_cT, D5, nullptr,
                       cross_b, M, HID, HID, 1, 0, HID, 0, 0, 0);
    GM<0, EP_F16_ACCUM>(X, WT + o_cB, D5, P1, nullptr,
                        M, HID, HID, 1, 0, HID, 0, 0, 0);        // new_emb2 -> P1

    // ---- layer 1, graph 1 (fused aW|uW, N=4096, K=2048) ----
    GM<0, EP_GCONV>(P0, WT + o_g1a, D1, XA,
                    g1_ab, M, 4096, HID, 1, 0, HID, 0, 0, 0, nullptr, nullptr, g1_ub);
    GM<1, EP_F16_ACCUM>(AN1, XA, D1, E1, nullptr,
                        256, HID, 256, 64, HID, HID, sNN, sNH, sNH);

    // ---- layer 1, graph 2 ----
    GM<0, EP_GCONV>(P1, WT + o_g1a, D2, XA,
                    g1_ab, M, 4096, HID, 1, 0, HID, 0, 0, 0, nullptr, nullptr, g1_ub);
    GM<1, EP_F16_ACCUM>(AN2, XA, D2, E2, nullptr,
                        256, HID, 256, 64, HID, HID, sNN, sNH, sNH);

    // ---- affinity 1 + Sinkhorn 2 -> out ----
    GM<0, EP_F16>(E1, WT + o_af1, nullptr, X, nullptr,
                  M, HID, HID, 1, 0, HID, 0, 0, 0);
    GM<0, EP_F32_MASK>(X, E2, S, nullptr, nullptr,
                       256, 256, HID, 64, 0, 256, sNH, sNH, sNN, n1, n2);
    for (int it = 0; it < 10; ++it) {
        if (!(it & 1))    sk_row<<<2048, 256>>>(S, n1);
        else if (it == 9) sk_col<1><<<dim3(8, 64), 256>>>(S, n2, out, nullptr, nullptr);
        else              sk_col<0><<<dim3(8, 64), 256>>>(S, n2, nullptr, nullptr, nullptr);
    }
}

// round 15
// speedup vs baseline: 1.2026x; 1.2026x over previous
#include <cuda_runtime.h>
#include <cuda_fp16.h>
#include <math.h>
#include <stdint.h>

#define NEGV (-1e30f)

// ========================= static device scratch ============================
#define MAXMN (16384L * 2048L)
__device__ float g_D1[MAXMN];
__device__ float g_D2[MAXMN];
__device__ float g_D4[MAXMN];
__device__ float g_D5[MAXMN];
__device__ float g_S[64L * 256 * 256];
__device__ __half g_P0[MAXMN];
__device__ __half g_P1[MAXMN];
__device__ __half g_XA[MAXMN];
__device__ __half g_X[MAXMN];
__device__ __half g_E1[MAXMN];
__device__ __half g_E2[MAXMN];
#define SNN (64L * 256 * 256)
__device__ __half g_AN1[SNN];
__device__ __half g_AN2[SNN];
__device__ __half g_Sh[SNN];
__device__ __half g_STh[SNN];
#define WT_ELEMS 29360128L
__device__ __half g_WT[WT_ELEMS];

// ============================ PTX helpers ===================================
__device__ __forceinline__ uint32_t smem_u32(const void* p) {
    uint32_t a;
    asm("{ .reg .u64 t; cvta.to.shared.u64 t, %1; cvt.u32.u64 %0, t; }" : "=r"(a) : "l"(p));
    return a;
}
__device__ __forceinline__ void cpasync16(uint32_t dst, const void* src) {
    asm volatile("cp.async.cg.shared.global [%0], [%1], 16;" :: "r"(dst), "l"(src));
}
__device__ __forceinline__ void ldm4(uint32_t* r, uint32_t a) {
    asm volatile("ldmatrix.sync.aligned.m8n8.x4.shared.b16 {%0,%1,%2,%3}, [%4];"
                 : "=r"(r[0]), "=r"(r[1]), "=r"(r[2]), "=r"(r[3]) : "r"(a));
}
__device__ __forceinline__ void ldm4t(uint32_t* r, uint32_t a) {
    asm volatile("ldmatrix.sync.aligned.m8n8.x4.trans.shared.b16 {%0,%1,%2,%3}, [%4];"
                 : "=r"(r[0]), "=r"(r[1]), "=r"(r[2]), "=r"(r[3]) : "r"(a));
}
#define MMA(d, a, b0, b1)                                                    \
    asm volatile(                                                            \
        "mma.sync.aligned.m16n8k16.row.col.f32.f16.f16.f32 "                 \
        "{%0,%1,%2,%3}, {%4,%5,%6,%7}, {%8,%9}, {%0,%1,%2,%3};"              \
        : "+f"((d)[0]), "+f"((d)[1]), "+f"((d)[2]), "+f"((d)[3])             \
        : "r"((a)[0]), "r"((a)[1]), "r"((a)[2]), "r"((a)[3]),                \
          "r"(b0), "r"(b1))

// ==================== unified tensor-core fp16 GEMM =========================
// CTA 128x128, 8 warps of 64x32, K-step 32, 3-stage cp.async, 2 CTAs/SM.
// (256,2): regs ~128 — 3 CTAs/SM forced spills into the mainloop (R14).
enum {
    EP_F32_BIAS = 0,
    EP_F32_BIAS_RELU = 1,
    EP_F16 = 2,
    EP_F16_ACCUM = 3,
    EP_F32_MASK = 4,
    EP_GCONV = 5
};

#define MM_STAGE 20480
#define NSTAGE 3
#define MM_SMEM (NSTAGE * MM_STAGE)

template <int BTRANS, int EPI>
__global__ __launch_bounds__(256, 2) void gmma(
    const __half* __restrict__ Ah, const __half* __restrict__ Bh,
    float* __restrict__ Cf, __half* __restrict__ Oh,
    const float* __restrict__ bias, const float* __restrict__ bias2,
    int K, int ldB, int ldC,
    long sA, long sB, long sC,
    const int* __restrict__ n1p, const int* __restrict__ n2p)
{
    constexpr uint32_t BOFF = 10240;

    extern __shared__ char smem[];
    const uint32_t sb = smem_u32(smem);
    const int tid = threadIdx.x;
    const int wid = tid >> 5, lane = tid & 31;
    const int wm = wid >> 2, wn = wid & 3;
    const int m0 = blockIdx.y << 7;
    const int n0 = blockIdx.x << 7;
    const int bz = blockIdx.z;
    const int NC = K >> 5;

    const __half* Ab = Ah + (long)bz * sA;
    const __half* Bb = Bh + (long)bz * sB;

    auto loadstage = [&](int c) {
        const uint32_t st_ = sb + (uint32_t)(c % NSTAGE) * MM_STAGE;
        const int kc_ = c << 5;
#pragma unroll
        for (int j = 0; j < 2; ++j) {
            const int i = tid + j * 256;
            const int r = i >> 2, cg = i & 3;
            const uint32_t so = r * 80 + cg * 16;
            const long go = (long)(m0 + r) * K + kc_ + cg * 8;
            cpasync16(st_ + so, Ab + go);
        }
        if (BTRANS) {
#pragma unroll
            for (int j = 0; j < 2; ++j) {
                const int i = tid + j * 256;
                const int r = i >> 4, ch = i & 15;
                const uint32_t so = r * 272 + ch * 16;
                const long go = (long)(kc_ + r) * ldB + n0 + ch * 8;
                cpasync16(st_ + BOFF + so, Bb + go);
            }
        } else {
#pragma unroll
            for (int j = 0; j < 2; ++j) {
                const int i = tid + j * 256;
                const int r = i >> 2, cg = i & 3;
                const uint32_t so = r * 80 + cg * 16;
                const long go = (long)(n0 + r) * K + kc_ + cg * 8;
                cpasync16(st_ + BOFF + so, Bb + go);
            }
        }
        asm volatile("cp.async.commit_group;" ::: "memory");
    };

    float acc[4][4][4];
#pragma unroll
    for (int a = 0; a < 4; a++)
#pragma unroll
        for (int b = 0; b < 4; b++)
#pragma unroll
            for (int c = 0; c < 4; c++) acc[a][b][c] = 0.f;

    // preload stages 0..NSTAGE-2
#pragma unroll
    for (int p = 0; p < NSTAGE - 1; ++p)
        if (p < NC) loadstage(p);

    for (int c = 0; c < NC; ++c) {
        // prefetch into buffer freed by iteration c-1 (verified R6 pattern)
        if (c + NSTAGE - 1 < NC) loadstage(c + NSTAGE - 1);

        const int rem = NC - 1 - c;
        if (rem >= 2)      asm volatile("cp.async.wait_group 2;" ::: "memory");
        else if (rem == 1) asm volatile("cp.async.wait_group 1;" ::: "memory");
        else               asm volatile("cp.async.wait_group 0;" ::: "memory");
        __syncthreads();

        const uint32_t st = sb + (uint32_t)(c % NSTAGE) * MM_STAGE;
        const uint32_t aA = st + (uint32_t)(wm * 64 * 80 + (lane & 15) * 80 + (lane >> 4) * 16);

#pragma unroll
        for (int kk = 0; kk < 2; ++kk) {
            uint32_t bh[8];
            if (BTRANS) {
#pragma unroll
                for (int g = 0; g < 2; ++g) {
                    const uint32_t ro = (uint32_t)(kk * 16 + (lane & 7) + ((lane >> 4) << 3)) * 272;
                    const uint32_t co = (uint32_t)(wn * 32 + g * 16 + (((lane >> 3) & 1) << 3)) * 2;
                    ldm4t(&bh[g * 4], st + BOFF + ro + co);
                }
            } else {
                const uint32_t aB = st + BOFF +
                    (uint32_t)(wn * 32 * 80 + (lane & 15) * 80 + (lane >> 4) * 16);
#pragma unroll
                for (int g = 0; g < 2; ++g)
                    ldm4(&bh[g * 4], aB + g * 1280 + kk * 32);
            }
#pragma unroll
            for (int mt = 0; mt < 4; ++mt) {
                uint32_t ah[4];
                ldm4(ah, aA + mt * 1280 + kk * 32);
#pragma unroll
                for (int nt = 0; nt < 4; ++nt) {
                    const int g = nt >> 1, o = nt & 1;
                    MMA(acc[mt][nt], ah, bh[g * 4 + o], bh[g * 4 + 2 + o]);
                }
            }
        }
        __syncthreads();
    }

    // ---- epilogue ----
    float* Cb = (Cf != nullptr) ? Cf + (long)bz * sC : nullptr;
    __half* Ohb = (Oh != nullptr) ? Oh + (long)bz * sC : nullptr;

    const int r_l = lane >> 2, c_l = (lane & 3) * 2;
    const int cb = n0 + wn * 32 + c_l;
    int r1 = 0, r2 = 0;
    if (EPI == EP_F32_MASK) { r1 = n1p[bz]; r2 = n2p[bz]; }
    const bool gconv_f16_half = (EPI == EP_GCONV) && (n0 < 2048);

#pragma unroll
    for (int mt = 0; mt < 4; ++mt) {
#pragma unroll
        for (int h = 0; h < 2; ++h) {
            const int row = m0 + wm * 64 + mt * 16 + h * 8 + r_l;
            const long rbase = (long)row * ldC;
#pragma unroll
            for (int nt = 0; nt < 4; ++nt) {
                float vx = acc[mt][nt][h * 2 + 0];
                float vy = acc[mt][nt][h * 2 + 1];
                const int col = cb + nt * 8;
                if (EPI == EP_GCONV) {
                    if (gconv_f16_half) {
                        vx = fmaxf(vx + bias[col], 0.f);
                        vy = fmaxf(vy + bias[col + 1], 0.f);
                        *(__half2*)(Ohb + rbase + col) =
                            __halves2half2(__float2half(vx), __float2half(vy));
                    } else {
                        float2 v;
                        v.x = fmaxf(vx + bias2[col - 2048], 0.f);
                        v.y = fmaxf(vy + bias2[col - 2047], 0.f);
                        *(float2*)(Cb + rbase + col - 2048) = v;
                    }
                    continue;
                }
                if (EPI == EP_F32_BIAS || EPI == EP_F32_BIAS_RELU) {
                    vx += bias[col];
                    vy += bias[col + 1];
                }
                if (EPI == EP_F32_BIAS_RELU) {
                    vx = fmaxf(vx, 0.f);
                    vy = fmaxf(vy, 0.f);
                }
                if (EPI == EP_F16_ACCUM) {
                    const float2 o = *(const float2*)(Cb + rbase + col);
                    vx += o.x;
                    vy += o.y;
                }
                if (EPI == EP_F32_MASK) {
                    const bool rv = row < r1;
                    vx = (rv && (col + 0) < r2) ? vx : NEGV;
                    vy = (rv && (col + 1) < r2) ? vy : NEGV;
                }
                if (EPI == EP_F32_BIAS || EPI == EP_F32_BIAS_RELU || EPI == EP_F32_MASK) {
                    float2 v;
                    v.x = vx;
                    v.y = vy;
                    *(float2*)(Cb + rbase + col) = v;
                } else {
                    *(__half2*)(Ohb + rbase + col) =
                        __halves2half2(__float2half(vx), __float2half(vy));
                }
            }
        }
    }
}

// =================== fp32 -> fp16 convert (feat only) =======================
__global__ void split_k(const float* __restrict__ x, __half* __restrict__ o, long n4)
{
    const long i = (long)blockIdx.x * blockDim.x + threadIdx.x;
    if (i >= n4) return;
    const float4 v = ((const float4*)x)[i];
    ((__half2*)o)[i * 2 + 0] = __halves2half2(__float2half(v.x), __float2half(v.y));
    ((__half2*)o)[i * 2 + 1] = __halves2half2(__float2half(v.z), __float2half(v.w));
}

// ============ weight transpose + fp16: W[K,N] -> [N,K] ======================
__global__ void tconv_k(const float* __restrict__ W, __half* __restrict__ o,
                        int K, int N)
{
    __shared__ float t[32][33];
    const int n0 = blockIdx.x << 5, k0 = blockIdx.y << 5;
    const int tx = threadIdx.x, ty = threadIdx.y;
#pragma unroll
    for (int r = 0; r < 4; ++r)
        t[ty + 8 * r][tx] = W[(long)(k0 + ty + 8 * r) * N + n0 + tx];
    __syncthreads();
#pragma unroll
    for (int r = 0; r < 4; ++r)
        o[(long)(n0 + ty + 8 * r) * K + k0 + tx] = __float2half(t[tx][ty + 8 * r]);
}

// ------ fused: column-L1-sum + normalized-A fp16 ----------------------------
__global__ void anprep_k(const float* __restrict__ A, __half* __restrict__ o)
{
    const int b = blockIdx.x, j = threadIdx.x;
    const long base = (long)b << 16;
    float s = 0.f;
#pragma unroll 8
    for (int i = 0; i < 256; i++) s += fabsf(A[base + i * 256 + j]);
    const float c = 1.f / fmaxf(s, 1e-12f);
#pragma unroll 4
    for (int i = 0; i < 256; i++)
        o[base + i * 256 + j] = __float2half(A[base + i * 256 + j] * c);
}

// ------------------- Sinkhorn row normalization (one warp per row) ---------
__global__ void sk_row(float* __restrict__ S, const int* __restrict__ n1)
{
    const int warp = (blockIdx.x * blockDim.x + threadIdx.x) >> 5;
    const int lane = threadIdx.x & 31;
    const int b = warp >> 8, i = warp & 255;
    if (i >= n1[b]) return;

    float4* row = (float4*)(S + (((long)(b * 256 + i)) << 8));
    float4 v0 = row[lane];
    float4 v1 = row[lane + 32];

    float m = fmaxf(fmaxf(fmaxf(v0.x, v0.y), fmaxf(v0.z, v0.w)),
                    fmaxf(fmaxf(v1.x, v1.y), fmaxf(v1.z, v1.w)));
#pragma unroll
    for (int o = 16; o; o >>= 1) m = fmaxf(m, __shfl_xor_sync(0xffffffffu, m, o));

    float s = expf(v0.x - m) + expf(v0.y - m) + expf(v0.z - m) + expf(v0.w - m)
            + expf(v1.x - m) + expf(v1.y - m) + expf(v1.z - m) + expf(v1.w - m);
#pragma unroll
    for (int o = 16; o; o >>= 1) s += __shfl_xor_sync(0xffffffffu, s, o);

    const float lse = m + logf(s);
    v0.x -= lse; v0.y -= lse; v0.z -= lse; v0.w -= lse;
    v1.x -= lse; v1.y -= lse; v1.z -= lse; v1.w -= lse;
    row[lane] = v0;
    row[lane + 32] = v1;
}

// --------- Sinkhorn column pass.  MODE 0: inner; 1: final->fp32 out;
// --------- 2: final-> S, S^T fp16                                 -----------
template <int MODE>
__global__ void sk_col(float* __restrict__ S, const int* __restrict__ n2,
                       float* __restrict__ out,
                       __half* __restrict__ Sh, __half* __restrict__ STh)
{
    const int b = blockIdx.y;
    const int tx = threadIdx.x & 31;
    const int ty = threadIdx.x >> 5;
    const int j = (blockIdx.x << 5) + tx;

    float* base = S + ((long)b << 16);
    float v[32];
#pragma unroll
    for (int r = 0; r < 32; r++) v[r] = base[(ty * 32 + r) * 256 + j];

    float m = -3.4e38f;
#pragma unroll
    for (int r = 0; r < 32; r++) m = fmaxf(m, v[r]);

    __shared__ float red[8][32];
    red[ty][tx] = m;
    __syncthreads();
    float mt = red[0][tx];
#pragma unroll
    for (int k = 1; k < 8; k++) mt = fmaxf(mt, red[k][tx]);

    float s = 0.f;
#pragma unroll
    for (int r = 0; r < 32; r++) s += expf(v[r] - mt);
    __syncthreads();
    red[ty][tx] = s;
    __syncthreads();
    float st = red[0][tx];
#pragma unroll
    for (int k = 1; k < 8; k++) st += red[k][tx];

    const float lse = mt + logf(st);
    const bool cv = j < n2[b];

    if (MODE == 1) {
        float* ob = out + ((long)b << 16);
#pragma unroll
        for (int r = 0; r < 32; r++)
            ob[(ty * 32 + r) * 256 + j] = cv ? expf(v[r] - lse) : 0.f;
    } else if (MODE == 2) {
        const long bb = (long)b << 16;
#pragma unroll
        for (int r = 0; r < 32; r++) {
            const int rg = ty * 32 + r;
            const float e = cv ? expf(v[r] - lse) : 0.f;
            const __half h = __float2half(e);
            Sh[bb + rg * 256 + j] = h;
            STh[bb + (long)j * 256 + rg] = h;
        }
    } else {
        if (cv) {
#pragma unroll
            for (int r = 0; r < 32; r++) base[(ty * 32 + r) * 256 + j] = v[r] - lse;
        }
    }
}

// ---------------------------- host-side helpers ----------------------------
typedef __half hf;

template <int BT, int EPI>
static inline void GM(const hf* Ah, const hf* Bh,
                      float* Cf, hf* Oh, const float* bias,
                      int M, int N, int K, int batch, int ldB, int ldC,
                      long sA, long sB, long sC,
                      const int* n1 = nullptr, const int* n2 = nullptr,
                      const float* bias2 = nullptr)
{
    cudaFuncSetAttribute(gmma<BT, EPI>, cudaFuncAttributeMaxDynamicSharedMemorySize, MM_SMEM);
    dim3 grid(N / 128, M / 128, batch);
    gmma<BT, EPI><<<grid, 256, MM_SMEM>>>(Ah, Bh, Cf, Oh, bias, bias2,
                                          K, ldB, ldC, sA, sB, sC, n1, n2);
}

static inline void SPLIT(const float* x, hf* o, long n)
{
    const long n4 = n >> 2;
    split_k<<<(unsigned)((n4 + 255) / 256), 256>>>(x, o, n4);
}

static inline void TCONV(const float* W, hf* o, int K, int N)
{
    dim3 grid(N / 32, K / 32);
    tconv_k<<<grid, dim3(32, 8)>>>(W, o, K, N);
}

extern "C" void kernel_launch(void* const* d_in, const int* in_sizes, int n_in,
                              void* d_out, int out_size)
{
    const float* feat1   = (const float*)d_in[0];
    const float* feat2   = (const float*)d_in[1];
    const float* A1      = (const float*)d_in[2];
    const float* A2      = (const float*)d_in[3];
    const float* g0_aW   = (const float*)d_in[4];
    const float* g0_ab   = (const float*)d_in[5];
    const float* g0_uW   = (const float*)d_in[6];
    const float* g0_ub   = (const float*)d_in[7];
    const float* g1_aW   = (const float*)d_in[8];
    const float* g1_ab   = (const float*)d_in[9];
    const float* g1_uW   = (const float*)d_in[10];
    const float* g1_ub   = (const float*)d_in[11];
    const float* aff0_W  = (const float*)d_in[12];
    const float* aff1_W  = (const float*)d_in[13];
    const float* cross_W = (const float*)d_in[14];
    const float* cross_b = (const float*)d_in[15];
    const int*   n1      = (const int*)d_in[16];
    const int*   n2      = (const int*)d_in[17];
    float*       out     = (float*)d_out;

    float *D1, *D2, *D4, *D5, *S;
    hf *P0, *P1, *XA, *X, *E1, *E2, *AN1, *AN2, *Sh, *STh, *WT;
    cudaGetSymbolAddress((void**)&D1, g_D1);
    cudaGetSymbolAddress((void**)&D2, g_D2);
    cudaGetSymbolAddress((void**)&D4, g_D4);
    cudaGetSymbolAddress((void**)&D5, g_D5);
    cudaGetSymbolAddress((void**)&S, g_S);
    cudaGetSymbolAddress((void**)&P0, g_P0);
    cudaGetSymbolAddress((void**)&P1, g_P1);
    cudaGetSymbolAddress((void**)&XA, g_XA);
    cudaGetSymbolAddress((void**)&X, g_X);
    cudaGetSymbolAddress((void**)&E1, g_E1);
    cudaGetSymbolAddress((void**)&E2, g_E2);
    cudaGetSymbolAddress((void**)&AN1, g_AN1);
    cudaGetSymbolAddress((void**)&AN2, g_AN2);
    cudaGetSymbolAddress((void**)&Sh, g_Sh);
    cudaGetSymbolAddress((void**)&STh, g_STh);
    cudaGetSymbolAddress((void**)&WT, g_WT);

    const int IN = 1024, HID = 2048;
    const int M = 16384;
    const long sNN = 65536;
    const long sNH = 524288;

    const long o_g0a = 0, o_g0u = 2097152, o_g1a = 4194304, o_g1u = 8388608;
    const long o_af0 = 12582912, o_af1 = 16777216, o_cT = 20971520, o_cB = 25165824;

    // ---- prologue: launch index 3 is a big fc gmma (capture lands at 3) ----
    TCONV(g0_aW, WT + o_g0a, IN, HID);        // 0
    SPLIT(feat1, P0, (long)M * IN);           // 1
    TCONV(g0_uW, WT + o_g0u, IN, HID);        // 2

    // ---- layer 0, graph 1 (fused aW|uW, N=4096) ----
    GM<0, EP_GCONV>(P0, WT + o_g0a, D1, XA,
                    g0_ab, M, 4096, IN, 1, 0, HID, 0, 0, 0, nullptr, nullptr, g0_ub);  // 3
    anprep_k<<<64, 256>>>(A1, AN1);
    GM<1, EP_F16_ACCUM>(AN1, XA, D1, E1, nullptr,
                        256, HID, 256, 64, HID, HID, sNN, sNH, sNH);

    // ---- layer 0, graph 2 ----
    SPLIT(feat2, P1, (long)M * IN);
    GM<0, EP_GCONV>(P1, WT + o_g0a, D2, XA,
                    g0_ab, M, 4096, IN, 1, 0, HID, 0, 0, 0, nullptr, nullptr, g0_ub);
    anprep_k<<<64, 256>>>(A2, AN2);
    GM<1, EP_F16_ACCUM>(AN2, XA, D2, E2, nullptr,
                        256, HID, 256, 64, HID, HID, sNN, sNH, sNH);

    // remaining weight prep
    TCONV(g1_aW, WT + o_g1a, HID, HID);
    TCONV(g1_uW, WT + o_g1u, HID, HID);
    TCONV(aff0_W, WT + o_af0, HID, HID);
    TCONV(aff1_W, WT + o_af1, HID, HID);
    TCONV(cross_W, WT + o_cT, HID, HID);
    TCONV(cross_W + (long)HID * HID, WT + o_cB, HID, HID);

    // ---- affinity 0 + Sinkhorn 1 (emits S, S^T fp16) ----
    GM<0, EP_F16>(E1, WT + o_af0, nullptr, X, nullptr,
                  M, HID, HID, 1, 0, HID, 0, 0, 0);
    GM<0, EP_F32_MASK>(X, E2, S, nullptr, nullptr,
                       256, 256, HID, 64, 0, 256, sNH, sNH, sNN, n1, n2);
    for (int it = 0; it < 10; ++it) {
        if (!(it & 1))    sk_row<<<2048, 256>>>(S, n1);
        else if (it == 9) sk_col<2><<<dim3(8, 64), 256>>>(S, n2, nullptr, Sh, STh);
        else              sk_col<0><<<dim3(8, 64), 256>>>(S, n2, nullptr, nullptr, nullptr);
    }

    // ---- cross-graph update ----
    GM<1, EP_F16>(Sh, E2, nullptr, X, nullptr,
                  256, HID, 256, 64, HID, HID, sNN, sNH, sNH);   // S @ emb2
    GM<0, EP_F32_BIAS>(E1, WT + o_cT, D4, nullptr,
                       cross_b, M, HID, HID, 1, 0, HID, 0, 0, 0);
    GM<0, EP_F16_ACCUM>(X, WT + o_cB, D4, P0, nullptr,
                        M, HID, HID, 1, 0, HID, 0, 0, 0);        // new_emb1 -> P0
    GM<1, EP_F16>(STh, E1, nullptr, X, nullptr,
                  256, HID, 256, 64, HID, HID, sNN, sNH, sNH);   // S^T @ emb1
    GM<0, EP_F32_BIAS>(E2, WT + o_cT, D5, nullptr,
                       cross_b, M, HID, HID, 1, 0, HID, 0, 0, 0);
    GM<0, EP_F16_ACCUM>(X, WT + o_cB, D5, P1, nullptr,
                        M, HID, HID, 1, 0, HID, 0, 0, 0);        // new_emb2 -> P1

    // ---- layer 1, graph 1 (fused aW|uW, N=4096, K=2048) ----
    GM<0, EP_GCONV>(P0, WT + o_g1a, D1, XA,
                    g1_ab, M, 4096, HID, 1, 0, HID, 0, 0, 0, nullptr, nullptr, g1_ub);
    GM<1, EP_F16_ACCUM>(AN1, XA, D1, E1, nullptr,
                        256, HID, 256, 64, HID, HID, sNN, sNH, sNH);

    // ---- layer 1, graph 2 ----
    GM<0, EP_GCONV>(P1, WT + o_g1a, D2, XA,
                    g1_ab, M, 4096, HID, 1, 0, HID, 0, 0, 0, nullptr, nullptr, g1_ub);
    GM<1, EP_F16_ACCUM>(AN2, XA, D2, E2, nullptr,
                        256, HID, 256, 64, HID, HID, sNN, sNH, sNH);

    // ---- affinity 1 + Sinkhorn 2 -> out ----
    GM<0, EP_F16>(E1, WT + o_af1, nullptr, X, nullptr,
                  M, HID, HID, 1, 0, HID, 0, 0, 0);
    GM<0, EP_F32_MASK>(X, E2, S, nullptr, nullptr,
                       256, 256, HID, 64, 0, 256, sNH, sNH, sNN, n1, n2);
    for (int it = 0; it < 10; ++it) {
        if (!(it & 1))    sk_row<<<2048, 256>>>(S, n1);
        else if (it == 9) sk_col<1><<<dim3(8, 64), 256>>>(S, n2, out, nullptr, nullptr);
        else              sk_col<0><<<dim3(8, 64), 256>>>(S, n2, nullptr, nullptr, nullptr);
    }
}

// round 16
// speedup vs baseline: 1.2072x; 1.0038x over previous
#include <cuda_runtime.h>
#include <cuda_fp16.h>
#include <math.h>
#include <stdint.h>

#define NEGV (-1e30f)

// ========================= static device scratch ============================
#define MAXMN (16384L * 2048L)
__device__ float g_D1[MAXMN];
__device__ float g_D2[MAXMN];
__device__ float g_D4[MAXMN];
__device__ float g_D5[MAXMN];
__device__ float g_S[64L * 256 * 256];
__device__ __half g_P0[MAXMN];
__device__ __half g_P1[MAXMN];
__device__ __half g_XA[MAXMN];
__device__ __half g_X[MAXMN];
__device__ __half g_E1[MAXMN];
__device__ __half g_E2[MAXMN];
#define SNN (64L * 256 * 256)
__device__ __half g_AN1[SNN];
__device__ __half g_AN2[SNN];
__device__ __half g_Sh[SNN];
__device__ __half g_STh[SNN];
#define WT_ELEMS 29360128L
__device__ __half g_WT[WT_ELEMS];

// ============================ PTX helpers ===================================
__device__ __forceinline__ uint32_t smem_u32(const void* p) {
    uint32_t a;
    asm("{ .reg .u64 t; cvta.to.shared.u64 t, %1; cvt.u32.u64 %0, t; }" : "=r"(a) : "l"(p));
    return a;
}
__device__ __forceinline__ void cpasync16(uint32_t dst, const void* src) {
    asm volatile("cp.async.cg.shared.global [%0], [%1], 16;" :: "r"(dst), "l"(src));
}
__device__ __forceinline__ void ldm4(uint32_t* r, uint32_t a) {
    asm volatile("ldmatrix.sync.aligned.m8n8.x4.shared.b16 {%0,%1,%2,%3}, [%4];"
                 : "=r"(r[0]), "=r"(r[1]), "=r"(r[2]), "=r"(r[3]) : "r"(a));
}
__device__ __forceinline__ void ldm4t(uint32_t* r, uint32_t a) {
    asm volatile("ldmatrix.sync.aligned.m8n8.x4.trans.shared.b16 {%0,%1,%2,%3}, [%4];"
                 : "=r"(r[0]), "=r"(r[1]), "=r"(r[2]), "=r"(r[3]) : "r"(a));
}
#define MMA(d, a, b0, b1)                                                    \
    asm volatile(                                                            \
        "mma.sync.aligned.m16n8k16.row.col.f32.f16.f16.f32 "                 \
        "{%0,%1,%2,%3}, {%4,%5,%6,%7}, {%8,%9}, {%0,%1,%2,%3};"              \
        : "+f"((d)[0]), "+f"((d)[1]), "+f"((d)[2]), "+f"((d)[3])             \
        : "r"((a)[0]), "r"((a)[1]), "r"((a)[2]), "r"((a)[3]),                \
          "r"(b0), "r"(b1))

// ==================== unified tensor-core fp16 GEMM =========================
// CTA 128x128, 512 threads: 16 warps of 32x32 (4x4 warp grid), K-step 32,
// 2-stage cp.async. Small warp tile -> ~60 regs -> 2 CTAs/SM = 32 warps/SM
// (double the latency coverage of the 8-warp/64x32 shape at equal MMA count).
enum {
    EP_F32_BIAS = 0,
    EP_F32_BIAS_RELU = 1,
    EP_F16 = 2,
    EP_F16_ACCUM = 3,
    EP_F32_MASK = 4,
    EP_GCONV = 5
};

#define MM_STAGE 20480
#define NSTAGE 2
#define MM_SMEM (NSTAGE * MM_STAGE)

template <int BTRANS, int EPI>
__global__ __launch_bounds__(512, 2) void gmma(
    const __half* __restrict__ Ah, const __half* __restrict__ Bh,
    float* __restrict__ Cf, __half* __restrict__ Oh,
    const float* __restrict__ bias, const float* __restrict__ bias2,
    int K, int ldB, int ldC,
    long sA, long sB, long sC,
    const int* __restrict__ n1p, const int* __restrict__ n2p)
{
    constexpr uint32_t BOFF = 10240;

    extern __shared__ char smem[];
    const uint32_t sb = smem_u32(smem);
    const int tid = threadIdx.x;
    const int wid = tid >> 5, lane = tid & 31;
    const int wm = wid >> 2, wn = wid & 3;   // 4x4 warp grid: 32-row x 32-col tiles
    const int m0 = blockIdx.y << 7;
    const int n0 = blockIdx.x << 7;
    const int bz = blockIdx.z;
    const int NC = K >> 5;

    const __half* Ab = Ah + (long)bz * sA;
    const __half* Bb = Bh + (long)bz * sB;

    auto loadstage = [&](int c) {
        const uint32_t st_ = sb + (uint32_t)(c % NSTAGE) * MM_STAGE;
        const int kc_ = c << 5;
        {   // A: 128 rows x 4 chunks of 16B -> exactly 512 loads
            const int r = tid >> 2, cg = tid & 3;
            const uint32_t so = r * 80 + cg * 16;
            const long go = (long)(m0 + r) * K + kc_ + cg * 8;
            cpasync16(st_ + so, Ab + go);
        }
        if (BTRANS) {
            // B: 32 k-rows x 16 chunks of 16B -> exactly 512 loads
            const int r = tid >> 4, ch = tid & 15;
            const uint32_t so = r * 272 + ch * 16;
            const long go = (long)(kc_ + r) * ldB + n0 + ch * 8;
            cpasync16(st_ + BOFF + so, Bb + go);
        } else {
            const int r = tid >> 2, cg = tid & 3;
            const uint32_t so = r * 80 + cg * 16;
            const long go = (long)(n0 + r) * K + kc_ + cg * 8;
            cpasync16(st_ + BOFF + so, Bb + go);
        }
        asm volatile("cp.async.commit_group;" ::: "memory");
    };

    float acc[2][4][4];
#pragma unroll
    for (int a = 0; a < 2; a++)
#pragma unroll
        for (int b = 0; b < 4; b++)
#pragma unroll
            for (int c = 0; c < 4; c++) acc[a][b][c] = 0.f;

    loadstage(0);

    for (int c = 0; c < NC; ++c) {
        if (c + 1 < NC) loadstage(c + 1);

        if (c + 1 < NC) asm volatile("cp.async.wait_group 1;" ::: "memory");
        else            asm volatile("cp.async.wait_group 0;" ::: "memory");
        __syncthreads();

        const uint32_t st = sb + (uint32_t)(c % NSTAGE) * MM_STAGE;
        const uint32_t aA = st + (uint32_t)(wm * 32 * 80 + (lane & 15) * 80 + (lane >> 4) * 16);

#pragma unroll
        for (int kk = 0; kk < 2; ++kk) {
            uint32_t bh[8];
            if (BTRANS) {
#pragma unroll
                for (int g = 0; g < 2; ++g) {
                    const uint32_t ro = (uint32_t)(kk * 16 + (lane & 7) + ((lane >> 4) << 3)) * 272;
                    const uint32_t co = (uint32_t)(wn * 32 + g * 16 + (((lane >> 3) & 1) << 3)) * 2;
                    ldm4t(&bh[g * 4], st + BOFF + ro + co);
                }
            } else {
                const uint32_t aB = st + BOFF +
                    (uint32_t)(wn * 32 * 80 + (lane & 15) * 80 + (lane >> 4) * 16);
#pragma unroll
                for (int g = 0; g < 2; ++g)
                    ldm4(&bh[g * 4], aB + g * 1280 + kk * 32);
            }
#pragma unroll
            for (int mt = 0; mt < 2; ++mt) {
                uint32_t ah[4];
                ldm4(ah, aA + mt * 1280 + kk * 32);
#pragma unroll
                for (int nt = 0; nt < 4; ++nt) {
                    const int g = nt >> 1, o = nt & 1;
                    MMA(acc[mt][nt], ah, bh[g * 4 + o], bh[g * 4 + 2 + o]);
                }
            }
        }
        __syncthreads();
    }

    // ---- epilogue ----
    float* Cb = (Cf != nullptr) ? Cf + (long)bz * sC : nullptr;
    __half* Ohb = (Oh != nullptr) ? Oh + (long)bz * sC : nullptr;

    const int r_l = lane >> 2, c_l = (lane & 3) * 2;
    const int cb = n0 + wn * 32 + c_l;
    int r1 = 0, r2 = 0;
    if (EPI == EP_F32_MASK) { r1 = n1p[bz]; r2 = n2p[bz]; }
    const bool gconv_f16_half = (EPI == EP_GCONV) && (n0 < 2048);

#pragma unroll
    for (int mt = 0; mt < 2; ++mt) {
#pragma unroll
        for (int h = 0; h < 2; ++h) {
            const int row = m0 + wm * 32 + mt * 16 + h * 8 + r_l;
            const long rbase = (long)row * ldC;
#pragma unroll
            for (int nt = 0; nt < 4; ++nt) {
                float vx = acc[mt][nt][h * 2 + 0];
                float vy = acc[mt][nt][h * 2 + 1];
                const int col = cb + nt * 8;
                if (EPI == EP_GCONV) {
                    if (gconv_f16_half) {
                        vx = fmaxf(vx + bias[col], 0.f);
                        vy = fmaxf(vy + bias[col + 1], 0.f);
                        *(__half2*)(Ohb + rbase + col) =
                            __halves2half2(__float2half(vx), __float2half(vy));
                    } else {
                        float2 v;
                        v.x = fmaxf(vx + bias2[col - 2048], 0.f);
                        v.y = fmaxf(vy + bias2[col - 2047], 0.f);
                        *(float2*)(Cb + rbase + col - 2048) = v;
                    }
                    continue;
                }
                if (EPI == EP_F32_BIAS || EPI == EP_F32_BIAS_RELU) {
                    vx += bias[col];
                    vy += bias[col + 1];
                }
                if (EPI == EP_F32_BIAS_RELU) {
                    vx = fmaxf(vx, 0.f);
                    vy = fmaxf(vy, 0.f);
                }
                if (EPI == EP_F16_ACCUM) {
                    const float2 o = *(const float2*)(Cb + rbase + col);
                    vx += o.x;
                    vy += o.y;
                }
                if (EPI == EP_F32_MASK) {
                    const bool rv = row < r1;
                    vx = (rv && (col + 0) < r2) ? vx : NEGV;
                    vy = (rv && (col + 1) < r2) ? vy : NEGV;
                }
                if (EPI == EP_F32_BIAS || EPI == EP_F32_BIAS_RELU || EPI == EP_F32_MASK) {
                    float2 v;
                    v.x = vx;
                    v.y = vy;
                    *(float2*)(Cb + rbase + col) = v;
                } else {
                    *(__half2*)(Ohb + rbase + col) =
                        __halves2half2(__float2half(vx), __float2half(vy));
                }
            }
        }
    }
}

// =================== fp32 -> fp16 convert (feat only) =======================
__global__ void split_k(const float* __restrict__ x, __half* __restrict__ o, long n4)
{
    const long i = (long)blockIdx.x * blockDim.x + threadIdx.x;
    if (i >= n4) return;
    const float4 v = ((const float4*)x)[i];
    ((__half2*)o)[i * 2 + 0] = __halves2half2(__float2half(v.x), __float2half(v.y));
    ((__half2*)o)[i * 2 + 1] = __halves2half2(__float2half(v.z), __float2half(v.w));
}

// ============ weight transpose + fp16: W[K,N] -> [N,K] ======================
__global__ void tconv_k(const float* __restrict__ W, __half* __restrict__ o,
                        int K, int N)
{
    __shared__ float t[32][33];
    const int n0 = blockIdx.x << 5, k0 = blockIdx.y << 5;
    const int tx = threadIdx.x, ty = threadIdx.y;
#pragma unroll
    for (int r = 0; r < 4; ++r)
        t[ty + 8 * r][tx] = W[(long)(k0 + ty + 8 * r) * N + n0 + tx];
    __syncthreads();
#pragma unroll
    for (int r = 0; r < 4; ++r)
        o[(long)(n0 + ty + 8 * r) * K + k0 + tx] = __float2half(t[tx][ty + 8 * r]);
}

// ------ fused: column-L1-sum + normalized-A fp16 ----------------------------
__global__ void anprep_k(const float* __restrict__ A, __half* __restrict__ o)
{
    const int b = blockIdx.x, j = threadIdx.x;
    const long base = (long)b << 16;
    float s = 0.f;
#pragma unroll 8
    for (int i = 0; i < 256; i++) s += fabsf(A[base + i * 256 + j]);
    const float c = 1.f / fmaxf(s, 1e-12f);
#pragma unroll 4
    for (int i = 0; i < 256; i++)
        o[base + i * 256 + j] = __float2half(A[base + i * 256 + j] * c);
}

// ------------------- Sinkhorn row normalization (one warp per row) ---------
__global__ void sk_row(float* __restrict__ S, const int* __restrict__ n1)
{
    const int warp = (blockIdx.x * blockDim.x + threadIdx.x) >> 5;
    const int lane = threadIdx.x & 31;
    const int b = warp >> 8, i = warp & 255;
    if (i >= n1[b]) return;

    float4* row = (float4*)(S + (((long)(b * 256 + i)) << 8));
    float4 v0 = row[lane];
    float4 v1 = row[lane + 32];

    float m = fmaxf(fmaxf(fmaxf(v0.x, v0.y), fmaxf(v0.z, v0.w)),
                    fmaxf(fmaxf(v1.x, v1.y), fmaxf(v1.z, v1.w)));
#pragma unroll
    for (int o = 16; o; o >>= 1) m = fmaxf(m, __shfl_xor_sync(0xffffffffu, m, o));

    float s = expf(v0.x - m) + expf(v0.y - m) + expf(v0.z - m) + expf(v0.w - m)
            + expf(v1.x - m) + expf(v1.y - m) + expf(v1.z - m) + expf(v1.w - m);
#pragma unroll
    for (int o = 16; o; o >>= 1) s += __shfl_xor_sync(0xffffffffu, s, o);

    const float lse = m + logf(s);
    v0.x -= lse; v0.y -= lse; v0.z -= lse; v0.w -= lse;
    v1.x -= lse; v1.y -= lse; v1.z -= lse; v1.w -= lse;
    row[lane] = v0;
    row[lane + 32] = v1;
}

// --------- Sinkhorn column pass.  MODE 0: inner; 1: final->fp32 out;
// --------- 2: final-> S, S^T fp16                                 -----------
template <int MODE>
__global__ void sk_col(float* __restrict__ S, const int* __restrict__ n2,
                       float* __restrict__ out,
                       __half* __restrict__ Sh, __half* __restrict__ STh)
{
    const int b = blockIdx.y;
    const int tx = threadIdx.x & 31;
    const int ty = threadIdx.x >> 5;
    const int j = (blockIdx.x << 5) + tx;

    float* base = S + ((long)b << 16);
    float v[32];
#pragma unroll
    for (int r = 0; r < 32; r++) v[r] = base[(ty * 32 + r) * 256 + j];

    float m = -3.4e38f;
#pragma unroll
    for (int r = 0; r < 32; r++) m = fmaxf(m, v[r]);

    __shared__ float red[8][32];
    red[ty][tx] = m;
    __syncthreads();
    float mt = red[0][tx];
#pragma unroll
    for (int k = 1; k < 8; k++) mt = fmaxf(mt, red[k][tx]);

    float s = 0.f;
#pragma unroll
    for (int r = 0; r < 32; r++) s += expf(v[r] - mt);
    __syncthreads();
    red[ty][tx] = s;
    __syncthreads();
    float st = red[0][tx];
#pragma unroll
    for (int k = 1; k < 8; k++) st += red[k][tx];

    const float lse = mt + logf(st);
    const bool cv = j < n2[b];

    if (MODE == 1) {
        float* ob = out + ((long)b << 16);
#pragma unroll
        for (int r = 0; r < 32; r++)
            ob[(ty * 32 + r) * 256 + j] = cv ? expf(v[r] - lse) : 0.f;
    } else if (MODE == 2) {
        const long bb = (long)b << 16;
#pragma unroll
        for (int r = 0; r < 32; r++) {
            const int rg = ty * 32 + r;
            const float e = cv ? expf(v[r] - lse) : 0.f;
            const __half h = __float2half(e);
            Sh[bb + rg * 256 + j] = h;
            STh[bb + (long)j * 256 + rg] = h;
        }
    } else {
        if (cv) {
#pragma unroll
            for (int r = 0; r < 32; r++) base[(ty * 32 + r) * 256 + j] = v[r] - lse;
        }
    }
}

// ---------------------------- host-side helpers ----------------------------
typedef __half hf;

template <int BT, int EPI>
static inline void GM(const hf* Ah, const hf* Bh,
                      float* Cf, hf* Oh, const float* bias,
                      int M, int N, int K, int batch, int ldB, int ldC,
                      long sA, long sB, long sC,
                      const int* n1 = nullptr, const int* n2 = nullptr,
                      const float* bias2 = nullptr)
{
    cudaFuncSetAttribute(gmma<BT, EPI>, cudaFuncAttributeMaxDynamicSharedMemorySize, MM_SMEM);
    dim3 grid(N / 128, M / 128, batch);
    gmma<BT, EPI><<<grid, 512, MM_SMEM>>>(Ah, Bh, Cf, Oh, bias, bias2,
                                          K, ldB, ldC, sA, sB, sC, n1, n2);
}

static inline void SPLIT(const float* x, hf* o, long n)
{
    const long n4 = n >> 2;
    split_k<<<(unsigned)((n4 + 255) / 256), 256>>>(x, o, n4);
}

static inline void TCONV(const float* W, hf* o, int K, int N)
{
    dim3 grid(N / 32, K / 32);
    tconv_k<<<grid, dim3(32, 8)>>>(W, o, K, N);
}

extern "C" void kernel_launch(void* const* d_in, const int* in_sizes, int n_in,
                              void* d_out, int out_size)
{
    const float* feat1   = (const float*)d_in[0];
    const float* feat2   = (const float*)d_in[1];
    const float* A1      = (const float*)d_in[2];
    const float* A2      = (const float*)d_in[3];
    const float* g0_aW   = (const float*)d_in[4];
    const float* g0_ab   = (const float*)d_in[5];
    const float* g0_uW   = (const float*)d_in[6];
    const float* g0_ub   = (const float*)d_in[7];
    const float* g1_aW   = (const float*)d_in[8];
    const float* g1_ab   = (const float*)d_in[9];
    const float* g1_uW   = (const float*)d_in[10];
    const float* g1_ub   = (const float*)d_in[11];
    const float* aff0_W  = (const float*)d_in[12];
    const float* aff1_W  = (const float*)d_in[13];
    const float* cross_W = (const float*)d_in[14];
    const float* cross_b = (const float*)d_in[15];
    const int*   n1      = (const int*)d_in[16];
    const int*   n2      = (const int*)d_in[17];
    float*       out     = (float*)d_out;

    float *D1, *D2, *D4, *D5, *S;
    hf *P0, *P1, *XA, *X, *E1, *E2, *AN1, *AN2, *Sh, *STh, *WT;
    cudaGetSymbolAddress((void**)&D1, g_D1);
    cudaGetSymbolAddress((void**)&D2, g_D2);
    cudaGetSymbolAddress((void**)&D4, g_D4);
    cudaGetSymbolAddress((void**)&D5, g_D5);
    cudaGetSymbolAddress((void**)&S, g_S);
    cudaGetSymbolAddress((void**)&P0, g_P0);
    cudaGetSymbolAddress((void**)&P1, g_P1);
    cudaGetSymbolAddress((void**)&XA, g_XA);
    cudaGetSymbolAddress((void**)&X, g_X);
    cudaGetSymbolAddress((void**)&E1, g_E1);
    cudaGetSymbolAddress((void**)&E2, g_E2);
    cudaGetSymbolAddress((void**)&AN1, g_AN1);
    cudaGetSymbolAddress((void**)&AN2, g_AN2);
    cudaGetSymbolAddress((void**)&Sh, g_Sh);
    cudaGetSymbolAddress((void**)&STh, g_STh);
    cudaGetSymbolAddress((void**)&WT, g_WT);

    const int IN = 1024, HID = 2048;
    const int M = 16384;
    const long sNN = 65536;
    const long sNH = 524288;

    const long o_g0a = 0, o_g0u = 2097152, o_g1a = 4194304, o_g1u = 8388608;
    const long o_af0 = 12582912, o_af1 = 16777216, o_cT = 20971520, o_cB = 25165824;

    // ---- prologue: launch index 3 is a big fc gmma (capture lands at 3) ----
    TCONV(g0_aW, WT + o_g0a, IN, HID);        // 0
    SPLIT(feat1, P0, (long)M * IN);           // 1
    TCONV(g0_uW, WT + o_g0u, IN, HID);        // 2

    // ---- layer 0, graph 1 (fused aW|uW, N=4096) ----
    GM<0, EP_GCONV>(P0, WT + o_g0a, D1, XA,
                    g0_ab, M, 4096, IN, 1, 0, HID, 0, 0, 0, nullptr, nullptr, g0_ub);  // 3
    anprep_k<<<64, 256>>>(A1, AN1);
    GM<1, EP_F16_ACCUM>(AN1, XA, D1, E1, nullptr,
                        256, HID, 256, 64, HID, HID, sNN, sNH, sNH);

    // ---- layer 0, graph 2 ----
    SPLIT(feat2, P1, (long)M * IN);
    GM<0, EP_GCONV>(P1, WT + o_g0a, D2, XA,
                    g0_ab, M, 4096, IN, 1, 0, HID, 0, 0, 0, nullptr, nullptr, g0_ub);
    anprep_k<<<64, 256>>>(A2, AN2);
    GM<1, EP_F16_ACCUM>(AN2, XA, D2, E2, nullptr,
                        256, HID, 256, 64, HID, HID, sNN, sNH, sNH);

    // remaining weight prep
    TCONV(g1_aW, WT + o_g1a, HID, HID);
    TCONV(g1_uW, WT + o_g1u, HID, HID);
    TCONV(aff0_W, WT + o_af0, HID, HID);
    TCONV(aff1_W, WT + o_af1, HID, HID);
    TCONV(cross_W, WT + o_cT, HID, HID);
    TCONV(cross_W + (long)HID * HID, WT + o_cB, HID, HID);

    // ---- affinity 0 + Sinkhorn 1 (emits S, S^T fp16) ----
    GM<0, EP_F16>(E1, WT + o_af0, nullptr, X, nullptr,
                  M, HID, HID, 1, 0, HID, 0, 0, 0);
    GM<0, EP_F32_MASK>(X, E2, S, nullptr, nullptr,
                       256, 256, HID, 64, 0, 256, sNH, sNH, sNN, n1, n2);
    for (int it = 0; it < 10; ++it) {
        if (!(it & 1))    sk_row<<<2048, 256>>>(S, n1);
        else if (it == 9) sk_col<2><<<dim3(8, 64), 256>>>(S, n2, nullptr, Sh, STh);
        else              sk_col<0><<<dim3(8, 64), 256>>>(S, n2, nullptr, nullptr, nullptr);
    }

    // ---- cross-graph update ----
    GM<1, EP_F16>(Sh, E2, nullptr, X, nullptr,
                  256, HID, 256, 64, HID, HID, sNN, sNH, sNH);   // S @ emb2
    GM<0, EP_F32_BIAS>(E1, WT + o_cT, D4, nullptr,
                       cross_b, M, HID, HID, 1, 0, HID, 0, 0, 0);
    GM<0, EP_F16_ACCUM>(X, WT + o_cB, D4, P0, nullptr,
                        M, HID, HID, 1, 0, HID, 0, 0, 0);        // new_emb1 -> P0
    GM<1, EP_F16>(STh, E1, nullptr, X, nullptr,
                  256, HID, 256, 64, HID, HID, sNN, sNH, sNH);   // S^T @ emb1
    GM<0, EP_F32_BIAS>(E2, WT + o_cT, D5, nullptr,
                       cross_b, M, HID, HID, 1, 0, HID, 0, 0, 0);
    GM<0, EP_F16_ACCUM>(X, WT + o_cB, D5, P1, nullptr,
                        M, HID, HID, 1, 0, HID, 0, 0, 0);        // new_emb2 -> P1

    // ---- layer 1, graph 1 (fused aW|uW, N=4096, K=2048) ----
    GM<0, EP_GCONV>(P0, WT + o_g1a, D1, XA,
                    g1_ab, M, 4096, HID, 1, 0, HID, 0, 0, 0, nullptr, nullptr, g1_ub);
    GM<1, EP_F16_ACCUM>(AN1, XA, D1, E1, nullptr,
                        256, HID, 256, 64, HID, HID, sNN, sNH, sNH);

    // ---- layer 1, graph 2 ----
    GM<0, EP_GCONV>(P1, WT + o_g1a, D2, XA,
                    g1_ab, M, 4096, HID, 1, 0, HID, 0, 0, 0, nullptr, nullptr, g1_ub);
    GM<1, EP_F16_ACCUM>(AN2, XA, D2, E2, nullptr,
                        256, HID, 256, 64, HID, HID, sNN, sNH, sNH);

    // ---- affinity 1 + Sinkhorn 2 -> out ----
    GM<0, EP_F16>(E1, WT + o_af1, nullptr, X, nullptr,
                  M, HID, HID, 1, 0, HID, 0, 0, 0);
    GM<0, EP_F32_MASK>(X, E2, S, nullptr, nullptr,
                       256, 256, HID, 64, 0, 256, sNH, sNH, sNN, n1, n2);
    for (int it = 0; it < 10; ++it) {
        if (!(it & 1))    sk_row<<<2048, 256>>>(S, n1);
        else if (it == 9) sk_col<1><<<dim3(8, 64), 256>>>(S, n2, out, nullptr, nullptr);
        else              sk_col<0><<<dim3(8, 64), 256>>>(S, n2, nullptr, nullptr, nullptr);
    }
}

// round 17
// speedup vs baseline: 1.2247x; 1.0145x over previous
#include <cuda_runtime.h>
#include <cuda_fp16.h>
#include <math.h>
#include <stdint.h>

#define NEGV (-1e30f)

// ========================= static device scratch ============================
#define MAXMN (16384L * 2048L)
__device__ float g_S[64L * 256 * 256];
__device__ __half g_P0[MAXMN];
__device__ __half g_P1[MAXMN];
__device__ __half g_XA[MAXMN];
__device__ __half g_U[MAXMN];
__device__ __half g_X[MAXMN];
__device__ __half g_E1[MAXMN];
__device__ __half g_E2[MAXMN];
#define SNN (64L * 256 * 256)
__device__ __half g_AN1[SNN];
__device__ __half g_AN2[SNN];
__device__ __half g_Sh[SNN];
__device__ __half g_STh[SNN];
#define WT_ELEMS 29360128L
__device__ __half g_WT[WT_ELEMS];

// ============================ PTX helpers ===================================
__device__ __forceinline__ uint32_t smem_u32(const void* p) {
    uint32_t a;
    asm("{ .reg .u64 t; cvta.to.shared.u64 t, %1; cvt.u32.u64 %0, t; }" : "=r"(a) : "l"(p));
    return a;
}
__device__ __forceinline__ void cpasync16(uint32_t dst, const void* src) {
    asm volatile("cp.async.cg.shared.global [%0], [%1], 16;" :: "r"(dst), "l"(src));
}
__device__ __forceinline__ void ldm4(uint32_t* r, uint32_t a) {
    asm volatile("ldmatrix.sync.aligned.m8n8.x4.shared.b16 {%0,%1,%2,%3}, [%4];"
                 : "=r"(r[0]), "=r"(r[1]), "=r"(r[2]), "=r"(r[3]) : "r"(a));
}
__device__ __forceinline__ void ldm4t(uint32_t* r, uint32_t a) {
    asm volatile("ldmatrix.sync.aligned.m8n8.x4.trans.shared.b16 {%0,%1,%2,%3}, [%4];"
                 : "=r"(r[0]), "=r"(r[1]), "=r"(r[2]), "=r"(r[3]) : "r"(a));
}
#define MMA(d, a, b0, b1)                                                    \
    asm volatile(                                                            \
        "mma.sync.aligned.m16n8k16.row.col.f32.f16.f16.f32 "                 \
        "{%0,%1,%2,%3}, {%4,%5,%6,%7}, {%8,%9}, {%0,%1,%2,%3};"              \
        : "+f"((d)[0]), "+f"((d)[1]), "+f"((d)[2]), "+f"((d)[3])             \
        : "r"((a)[0]), "r"((a)[1]), "r"((a)[2]), "r"((a)[3]),                \
          "r"(b0), "r"(b1))

// ==================== unified tensor-core fp16 GEMM =========================
// CTA 128x128, 512 threads (16 warps of 32x32), K-step 32, 2-stage cp.async.
// DUAL=1: K=4096 with per-half operand pointers (A and B switch at k=2048,
// sub-operand row stride 2048) — fused [E | X] @ [cT ; cB].
enum {
    EP_F16 = 0,
    EP_F16_BIAS = 1,
    EP_F16_ACCH = 2,
    EP_F32_MASK = 3,
    EP_GCONV = 4
};

#define MM_STAGE 20480
#define NSTAGE 2
#define MM_SMEM (NSTAGE * MM_STAGE)

template <int BTRANS, int DUAL, int EPI>
__global__ __launch_bounds__(512, 2) void gmma(
    const __half* __restrict__ Ah, const __half* __restrict__ Ah2,
    const __half* __restrict__ Bh, const __half* __restrict__ Bh2,
    float* __restrict__ Cf, __half* __restrict__ Oh, __half* __restrict__ Oh2,
    const __half* __restrict__ AccH,
    const float* __restrict__ bias, const float* __restrict__ bias2,
    int K, int ldB, int ldC,
    long sA, long sB, long sC,
    const int* __restrict__ n1p, const int* __restrict__ n2p)
{
    constexpr uint32_t BOFF = 10240;

    extern __shared__ char smem[];
    const uint32_t sb = smem_u32(smem);
    const int tid = threadIdx.x;
    const int wid = tid >> 5, lane = tid & 31;
    const int wm = wid >> 2, wn = wid & 3;
    const int m0 = blockIdx.y << 7;
    const int n0 = blockIdx.x << 7;
    const int bz = blockIdx.z;
    const int NC = K >> 5;

    const __half* Ab = Ah + (long)bz * sA;
    const __half* Bb = Bh + (long)bz * sB;

    auto loadstage = [&](int c) {
        const uint32_t st_ = sb + (uint32_t)(c % NSTAGE) * MM_STAGE;
        int kc_ = c << 5;
        const __half* As = Ab;
        const __half* Bs = Bb;
        if (DUAL && kc_ >= 2048) {
            As = Ah2;
            Bs = Bh2;
            kc_ -= 2048;
        }
        const int lda = DUAL ? 2048 : K;
        {   // A: 128 rows x 4 chunks of 16B -> exactly 512 loads
            const int r = tid >> 2, cg = tid & 3;
            const uint32_t so = r * 80 + cg * 16;
            const long go = (long)(m0 + r) * lda + kc_ + cg * 8;
            cpasync16(st_ + so, As + go);
        }
        if (BTRANS) {
            const int r = tid >> 4, ch = tid & 15;
            const uint32_t so = r * 272 + ch * 16;
            const long go = (long)(kc_ + r) * ldB + n0 + ch * 8;
            cpasync16(st_ + BOFF + so, Bs + go);
        } else {
            const int r = tid >> 2, cg = tid & 3;
            const uint32_t so = r * 80 + cg * 16;
            const long go = (long)(n0 + r) * lda + kc_ + cg * 8;
            cpasync16(st_ + BOFF + so, Bs + go);
        }
        asm volatile("cp.async.commit_group;" ::: "memory");
    };

    float acc[2][4][4];
#pragma unroll
    for (int a = 0; a < 2; a++)
#pragma unroll
        for (int b = 0; b < 4; b++)
#pragma unroll
            for (int c = 0; c < 4; c++) acc[a][b][c] = 0.f;

    loadstage(0);

    for (int c = 0; c < NC; ++c) {
        if (c + 1 < NC) loadstage(c + 1);

        if (c + 1 < NC) asm volatile("cp.async.wait_group 1;" ::: "memory");
        else            asm volatile("cp.async.wait_group 0;" ::: "memory");
        __syncthreads();

        const uint32_t st = sb + (uint32_t)(c % NSTAGE) * MM_STAGE;
        const uint32_t aA = st + (uint32_t)(wm * 32 * 80 + (lane & 15) * 80 + (lane >> 4) * 16);

#pragma unroll
        for (int kk = 0; kk < 2; ++kk) {
            uint32_t bh[8];
            if (BTRANS) {
#pragma unroll
                for (int g = 0; g < 2; ++g) {
                    const uint32_t ro = (uint32_t)(kk * 16 + (lane & 7) + ((lane >> 4) << 3)) * 272;
                    const uint32_t co = (uint32_t)(wn * 32 + g * 16 + (((lane >> 3) & 1) << 3)) * 2;
                    ldm4t(&bh[g * 4], st + BOFF + ro + co);
                }
            } else {
                const uint32_t aB = st + BOFF +
                    (uint32_t)(wn * 32 * 80 + (lane & 15) * 80 + (lane >> 4) * 16);
#pragma unroll
                for (int g = 0; g < 2; ++g)
                    ldm4(&bh[g * 4], aB + g * 1280 + kk * 32);
            }
#pragma unroll
            for (int mt = 0; mt < 2; ++mt) {
                uint32_t ah[4];
                ldm4(ah, aA + mt * 1280 + kk * 32);
#pragma unroll
                for (int nt = 0; nt < 4; ++nt) {
                    const int g = nt >> 1, o = nt & 1;
                    MMA(acc[mt][nt], ah, bh[g * 4 + o], bh[g * 4 + 2 + o]);
                }
            }
        }
        __syncthreads();
    }

    // ---- epilogue ----
    float* Cb = (Cf != nullptr) ? Cf + (long)bz * sC : nullptr;
    __half* Ohb = (Oh != nullptr) ? Oh + (long)bz * sC : nullptr;
    __half* Oh2b = (Oh2 != nullptr) ? Oh2 + (long)bz * sC : nullptr;
    const __half* Accb = (AccH != nullptr) ? AccH + (long)bz * sC : nullptr;

    const int r_l = lane >> 2, c_l = (lane & 3) * 2;
    const int cb = n0 + wn * 32 + c_l;
    int r1 = 0, r2 = 0;
    if (EPI == EP_F32_MASK) { r1 = n1p[bz]; r2 = n2p[bz]; }
    const bool gconv_upper = (EPI == EP_GCONV) && (n0 < 2048);

#pragma unroll
    for (int mt = 0; mt < 2; ++mt) {
#pragma unroll
        for (int h = 0; h < 2; ++h) {
            const int row = m0 + wm * 32 + mt * 16 + h * 8 + r_l;
            const long rbase = (long)row * ldC;
#pragma unroll
            for (int nt = 0; nt < 4; ++nt) {
                float vx = acc[mt][nt][h * 2 + 0];
                float vy = acc[mt][nt][h * 2 + 1];
                const int col = cb + nt * 8;
                if (EPI == EP_GCONV) {
                    if (gconv_upper) {
                        vx = fmaxf(vx + bias[col], 0.f);
                        vy = fmaxf(vy + bias[col + 1], 0.f);
                        *(__half2*)(Ohb + rbase + col) =
                            __halves2half2(__float2half(vx), __float2half(vy));
                    } else {
                        vx = fmaxf(vx + bias2[col - 2048], 0.f);
                        vy = fmaxf(vy + bias2[col - 2047], 0.f);
                        *(__half2*)(Oh2b + rbase + col - 2048) =
                            __halves2half2(__float2half(vx), __float2half(vy));
                    }
                    continue;
                }
                if (EPI == EP_F16_BIAS) {
                    vx += bias[col];
                    vy += bias[col + 1];
                }
                if (EPI == EP_F16_ACCH) {
                    const __half2 o = *(const __half2*)(Accb + rbase + col);
                    vx += __half2float(__low2half(o));
                    vy += __half2float(__high2half(o));
                }
                if (EPI == EP_F32_MASK) {
                    const bool rv = row < r1;
                    vx = (rv && (col + 0) < r2) ? vx : NEGV;
                    vy = (rv && (col + 1) < r2) ? vy : NEGV;
                    float2 v;
                    v.x = vx;
                    v.y = vy;
                    *(float2*)(Cb + rbase + col) = v;
                } else {
                    *(__half2*)(Ohb + rbase + col) =
                        __halves2half2(__float2half(vx), __float2half(vy));
                }
            }
        }
    }
}

// =================== fp32 -> fp16 convert (feat only) =======================
__global__ void split_k(const float* __restrict__ x, __half* __restrict__ o, long n4)
{
    const long i = (long)blockIdx.x * blockDim.x + threadIdx.x;
    if (i >= n4) return;
    const float4 v = ((const float4*)x)[i];
    ((__half2*)o)[i * 2 + 0] = __halves2half2(__float2half(v.x), __float2half(v.y));
    ((__half2*)o)[i * 2 + 1] = __halves2half2(__float2half(v.z), __float2half(v.w));
}

// ============ weight transpose + fp16: W[K,N] -> [N,K] ======================
__global__ void tconv_k(const float* __restrict__ W, __half* __restrict__ o,
                        int K, int N)
{
    __shared__ float t[32][33];
    const int n0 = blockIdx.x << 5, k0 = blockIdx.y << 5;
    const int tx = threadIdx.x, ty = threadIdx.y;
#pragma unroll
    for (int r = 0; r < 4; ++r)
        t[ty + 8 * r][tx] = W[(long)(k0 + ty + 8 * r) * N + n0 + tx];
    __syncthreads();
#pragma unroll
    for (int r = 0; r < 4; ++r)
        o[(long)(n0 + ty + 8 * r) * K + k0 + tx] = __float2half(t[tx][ty + 8 * r]);
}

// ------ fused: column-L1-sum + normalized-A fp16 ----------------------------
__global__ void anprep_k(const float* __restrict__ A, __half* __restrict__ o)
{
    const int b = blockIdx.x, j = threadIdx.x;
    const long base = (long)b << 16;
    float s = 0.f;
#pragma unroll 8
    for (int i = 0; i < 256; i++) s += fabsf(A[base + i * 256 + j]);
    const float c = 1.f / fmaxf(s, 1e-12f);
#pragma unroll 4
    for (int i = 0; i < 256; i++)
        o[base + i * 256 + j] = __float2half(A[base + i * 256 + j] * c);
}

// ------------------- Sinkhorn row normalization (one warp per row) ---------
__global__ void sk_row(float* __restrict__ S, const int* __restrict__ n1)
{
    const int warp = (blockIdx.x * blockDim.x + threadIdx.x) >> 5;
    const int lane = threadIdx.x & 31;
    const int b = warp >> 8, i = warp & 255;
    if (i >= n1[b]) return;

    float4* row = (float4*)(S + (((long)(b * 256 + i)) << 8));
    float4 v0 = row[lane];
    float4 v1 = row[lane + 32];

    float m = fmaxf(fmaxf(fmaxf(v0.x, v0.y), fmaxf(v0.z, v0.w)),
                    fmaxf(fmaxf(v1.x, v1.y), fmaxf(v1.z, v1.w)));
#pragma unroll
    for (int o = 16; o; o >>= 1) m = fmaxf(m, __shfl_xor_sync(0xffffffffu, m, o));

    float s = expf(v0.x - m) + expf(v0.y - m) + expf(v0.z - m) + expf(v0.w - m)
            + expf(v1.x - m) + expf(v1.y - m) + expf(v1.z - m) + expf(v1.w - m);
#pragma unroll
    for (int o = 16; o; o >>= 1) s += __shfl_xor_sync(0xffffffffu, s, o);

    const float lse = m + logf(s);
    v0.x -= lse; v0.y -= lse; v0.z -= lse; v0.w -= lse;
    v1.x -= lse; v1.y -= lse; v1.z -= lse; v1.w -= lse;
    row[lane] = v0;
    row[lane + 32] = v1;
}

// --------- Sinkhorn column pass.  MODE 0: inner; 1: final->fp32 out;
// --------- 2: final-> S, S^T fp16                                 -----------
template <int MODE>
__global__ void sk_col(float* __restrict__ S, const int* __restrict__ n2,
                       float* __restrict__ out,
                       __half* __restrict__ Sh, __half* __restrict__ STh)
{
    const int b = blockIdx.y;
    const int tx = threadIdx.x & 31;
    const int ty = threadIdx.x >> 5;
    const int j = (blockIdx.x << 5) + tx;

    float* base = S + ((long)b << 16);
    float v[32];
#pragma unroll
    for (int r = 0; r < 32; r++) v[r] = base[(ty * 32 + r) * 256 + j];

    float m = -3.4e38f;
#pragma unroll
    for (int r = 0; r < 32; r++) m = fmaxf(m, v[r]);

    __shared__ float red[8][32];
    red[ty][tx] = m;
    __syncthreads();
    float mt = red[0][tx];
#pragma unroll
    for (int k = 1; k < 8; k++) mt = fmaxf(mt, red[k][tx]);

    float s = 0.f;
#pragma unroll
    for (int r = 0; r < 32; r++) s += expf(v[r] - mt);
    __syncthreads();
    red[ty][tx] = s;
    __syncthreads();
    float st = red[0][tx];
#pragma unroll
    for (int k = 1; k < 8; k++) st += red[k][tx];

    const float lse = mt + logf(st);
    const bool cv = j < n2[b];

    if (MODE == 1) {
        float* ob = out + ((long)b << 16);
#pragma unroll
        for (int r = 0; r < 32; r++)
            ob[(ty * 32 + r) * 256 + j] = cv ? expf(v[r] - lse) : 0.f;
    } else if (MODE == 2) {
        const long bb = (long)b << 16;
#pragma unroll
        for (int r = 0; r < 32; r++) {
            const int rg = ty * 32 + r;
            const float e = cv ? expf(v[r] - lse) : 0.f;
            const __half h = __float2half(e);
            Sh[bb + rg * 256 + j] = h;
            STh[bb + (long)j * 256 + rg] = h;
        }
    } else {
        if (cv) {
#pragma unroll
            for (int r = 0; r < 32; r++) base[(ty * 32 + r) * 256 + j] = v[r] - lse;
        }
    }
}

// ---------------------------- host-side helpers ----------------------------
typedef __half hf;

template <int BT, int DUAL, int EPI>
static inline void GM(const hf* Ah, const hf* Ah2, const hf* Bh, const hf* Bh2,
                      float* Cf, hf* Oh, hf* Oh2, const hf* AccH,
                      const float* bias, const float* bias2,
                      int M, int N, int K, int batch, int ldB, int ldC,
                      long sA, long sB, long sC,
                      const int* n1 = nullptr, const int* n2 = nullptr)
{
    cudaFuncSetAttribute(gmma<BT, DUAL, EPI>, cudaFuncAttributeMaxDynamicSharedMemorySize, MM_SMEM);
    dim3 grid(N / 128, M / 128, batch);
    gmma<BT, DUAL, EPI><<<grid, 512, MM_SMEM>>>(Ah, Ah2, Bh, Bh2, Cf, Oh, Oh2, AccH,
                                                bias, bias2, K, ldB, ldC, sA, sB, sC, n1, n2);
}

static inline void SPLIT(const float* x, hf* o, long n)
{
    const long n4 = n >> 2;
    split_k<<<(unsigned)((n4 + 255) / 256), 256>>>(x, o, n4);
}

static inline void TCONV(const float* W, hf* o, int K, int N)
{
    dim3 grid(N / 32, K / 32);
    tconv_k<<<grid, dim3(32, 8)>>>(W, o, K, N);
}

extern "C" void kernel_launch(void* const* d_in, const int* in_sizes, int n_in,
                              void* d_out, int out_size)
{
    const float* feat1   = (const float*)d_in[0];
    const float* feat2   = (const float*)d_in[1];
    const float* A1      = (const float*)d_in[2];
    const float* A2      = (const float*)d_in[3];
    const float* g0_aW   = (const float*)d_in[4];
    const float* g0_ab   = (const float*)d_in[5];
    const float* g0_uW   = (const float*)d_in[6];
    const float* g0_ub   = (const float*)d_in[7];
    const float* g1_aW   = (const float*)d_in[8];
    const float* g1_ab   = (const float*)d_in[9];
    const float* g1_uW   = (const float*)d_in[10];
    const float* g1_ub   = (const float*)d_in[11];
    const float* aff0_W  = (const float*)d_in[12];
    const float* aff1_W  = (const float*)d_in[13];
    const float* cross_W = (const float*)d_in[14];
    const float* cross_b = (const float*)d_in[15];
    const int*   n1      = (const int*)d_in[16];
    const int*   n2      = (const int*)d_in[17];
    float*       out     = (float*)d_out;

    float *S;
    hf *P0, *P1, *XA, *U, *X, *E1, *E2, *AN1, *AN2, *Sh, *STh, *WT;
    cudaGetSymbolAddress((void**)&S, g_S);
    cudaGetSymbolAddress((void**)&P0, g_P0);
    cudaGetSymbolAddress((void**)&P1, g_P1);
    cudaGetSymbolAddress((void**)&XA, g_XA);
    cudaGetSymbolAddress((void**)&U, g_U);
    cudaGetSymbolAddress((void**)&X, g_X);
    cudaGetSymbolAddress((void**)&E1, g_E1);
    cudaGetSymbolAddress((void**)&E2, g_E2);
    cudaGetSymbolAddress((void**)&AN1, g_AN1);
    cudaGetSymbolAddress((void**)&AN2, g_AN2);
    cudaGetSymbolAddress((void**)&Sh, g_Sh);
    cudaGetSymbolAddress((void**)&STh, g_STh);
    cudaGetSymbolAddress((void**)&WT, g_WT);

    const int IN = 1024, HID = 2048;
    const int M = 16384;
    const long sNN = 65536;
    const long sNH = 524288;

    const long o_g0a = 0, o_g0u = 2097152, o_g1a = 4194304, o_g1u = 8388608;
    const long o_af0 = 12582912, o_af1 = 16777216, o_cT = 20971520, o_cB = 25165824;

    // ---- prologue: launch index 3 is a big fc gmma (capture lands at 3) ----
    TCONV(g0_aW, WT + o_g0a, IN, HID);        // 0
    SPLIT(feat1, P0, (long)M * IN);           // 1
    TCONV(g0_uW, WT + o_g0u, IN, HID);        // 2

    // ---- layer 0, graph 1 (fused aW|uW, N=4096; both halves f16) ----
    GM<0, 0, EP_GCONV>(P0, nullptr, WT + o_g0a, nullptr, nullptr, XA, U, nullptr,
                       g0_ab, g0_ub, M, 4096, IN, 1, 0, HID, 0, 0, 0);  // 3
    anprep_k<<<64, 256>>>(A1, AN1);
    GM<1, 0, EP_F16_ACCH>(AN1, nullptr, XA, nullptr, nullptr, E1, nullptr, U,
                          nullptr, nullptr, 256, HID, 256, 64, HID, HID, sNN, sNH, sNH);

    // ---- layer 0, graph 2 ----
    SPLIT(feat2, P1, (long)M * IN);
    GM<0, 0, EP_GCONV>(P1, nullptr, WT + o_g0a, nullptr, nullptr, XA, U, nullptr,
                       g0_ab, g0_ub, M, 4096, IN, 1, 0, HID, 0, 0, 0);
    anprep_k<<<64, 256>>>(A2, AN2);
    GM<1, 0, EP_F16_ACCH>(AN2, nullptr, XA, nullptr, nullptr, E2, nullptr, U,
                          nullptr, nullptr, 256, HID, 256, 64, HID, HID, sNN, sNH, sNH);

    // remaining weight prep
    TCONV(g1_aW, WT + o_g1a, HID, HID);
    TCONV(g1_uW, WT + o_g1u, HID, HID);
    TCONV(aff0_W, WT + o_af0, HID, HID);
    TCONV(aff1_W, WT + o_af1, HID, HID);
    TCONV(cross_W, WT + o_cT, HID, HID);
    TCONV(cross_W + (long)HID * HID, WT + o_cB, HID, HID);

    // ---- affinity 0 + Sinkhorn 1 (emits S, S^T fp16) ----
    GM<0, 0, EP_F16>(E1, nullptr, WT + o_af0, nullptr, nullptr, X, nullptr, nullptr,
                     nullptr, nullptr, M, HID, HID, 1, 0, HID, 0, 0, 0);
    GM<0, 0, EP_F32_MASK>(X, nullptr, E2, nullptr, S, nullptr, nullptr, nullptr,
                          nullptr, nullptr, 256, 256, HID, 64, 0, 256, sNH, sNH, sNN, n1, n2);
    for (int it = 0; it < 10; ++it) {
        if (!(it & 1))    sk_row<<<2048, 256>>>(S, n1);
        else if (it == 9) sk_col<2><<<dim3(8, 64), 256>>>(S, n2, nullptr, Sh, STh);
        else              sk_col<0><<<dim3(8, 64), 256>>>(S, n2, nullptr, nullptr, nullptr);
    }

    // ---- cross-graph update (fused dual-K GEMM: [E | S@E'] @ [cT;cB] + b) ----
    GM<1, 0, EP_F16>(Sh, nullptr, E2, nullptr, nullptr, X, nullptr, nullptr,
                     nullptr, nullptr, 256, HID, 256, 64, HID, HID, sNN, sNH, sNH);  // S @ emb2
    GM<0, 1, EP_F16_BIAS>(E1, X, WT + o_cT, WT + o_cB, nullptr, P0, nullptr, nullptr,
                          cross_b, nullptr, M, HID, 4096, 1, 0, HID, 0, 0, 0);       // new_emb1
    GM<1, 0, EP_F16>(STh, nullptr, E1, nullptr, nullptr, U, nullptr, nullptr,
                     nullptr, nullptr, 256, HID, 256, 64, HID, HID, sNN, sNH, sNH);  // S^T @ emb1
    GM<0, 1, EP_F16_BIAS>(E2, U, WT + o_cT, WT + o_cB, nullptr, P1, nullptr, nullptr,
                          cross_b, nullptr, M, HID, 4096, 1, 0, HID, 0, 0, 0);       // new_emb2

    // ---- layer 1, graph 1 (fused aW|uW, N=4096, K=2048) ----
    GM<0, 0, EP_GCONV>(P0, nullptr, WT + o_g1a, nullptr, nullptr, XA, U, nullptr,
                       g1_ab, g1_ub, M, 4096, HID, 1, 0, HID, 0, 0, 0);
    GM<1, 0, EP_F16_ACCH>(AN1, nullptr, XA, nullptr, nullptr, E1, nullptr, U,
                          nullptr, nullptr, 256, HID, 256, 64, HID, HID, sNN, sNH, sNH);

    // ---- layer 1, graph 2 ----
    GM<0, 0, EP_GCONV>(P1, nullptr, WT + o_g1a, nullptr, nullptr, XA, U, nullptr,
                       g1_ab, g1_ub, M, 4096, HID, 1, 0, HID, 0, 0, 0);
    GM<1, 0, EP_F16_ACCH>(AN2, nullptr, XA, nullptr, nullptr, E2, nullptr, U,
                          nullptr, nullptr, 256, HID, 256, 64, HID, HID, sNN, sNH, sNH);

    // ---- affinity 1 + Sinkhorn 2 -> out ----
    GM<0, 0, EP_F16>(E1, nullptr, WT + o_af1, nullptr, nullptr, X, nullptr, nullptr,
                     nullptr, nullptr, M, HID, HID, 1, 0, HID, 0, 0, 0);
    GM<0, 0, EP_F32_MASK>(X, nullptr, E2, nullptr, S, nullptr, nullptr, nullptr,
                          nullptr, nullptr, 256, 256, HID, 64, 0, 256, sNH, sNH, sNN, n1, n2);
    for (int it = 0; it < 10; ++it) {
        if (!(it & 1))    sk_row<<<2048, 256>>>(S, n1);
        else if (it == 9) sk_col<1><<<dim3(8, 64), 256>>>(S, n2, out, nullptr, nullptr);
        else              sk_col<0><<<dim3(8, 64), 256>>>(S, n2, nullptr, nullptr, nullptr);
    }
}